// round 1
// baseline (speedup 1.0000x reference)
#include <cuda_runtime.h>
#include <cuda_bf16.h>
#include <math.h>

#define N_NODES 80000
#define N_EDGES 640000
#define BATCH   800
#define NPG     100
#define HID     128
#define NC      10
#define IND     20
#define EPS     1e-5f

// ---------------- scratch (static device globals: allowed) ----------------
__device__ int   d_deg_in[N_NODES];
__device__ int   d_deg_out[N_NODES];
__device__ int   d_cls[N_NODES];
__device__ float d_inv_in[N_NODES];
__device__ float d_inv_out[N_NODES];

__device__ int   d_gcount[BATCH];
__device__ int   d_gcur[BATCH];
__device__ int   d_goff[BATCH + 1];
__device__ int   d_ebuck[N_EDGES];
__device__ int   d_esrc[N_EDGES];
__device__ int   d_off[N_NODES + 1];

__device__ float d_pre[N_NODES * HID];   // pre-activations (reused layer1/layer2)
__device__ float d_h1m[N_NODES * HID];   // elu(bn(l1)) * inv_out
__device__ float d_h2[N_NODES * HID];    // elu(bn(l2))
__device__ float d_t[N_NODES];           // inv_out * dot(h2, Wv)
__device__ float d_vec[BATCH * HID];
__device__ float d_hg0[BATCH * HID];
__device__ float d_z[BATCH * HID];

__device__ float d_bn1s[HID], d_bn1q[HID];
__device__ float d_bn2s[HID], d_bn2q[HID];
__device__ float d_bn3s[HID], d_bn3q[HID];
__device__ float d_meanAcc;

// ---------------- kernels ----------------

__global__ void k_zero() {
    int i = blockIdx.x * blockDim.x + threadIdx.x;
    if (i < N_NODES) { d_deg_in[i] = 0; d_deg_out[i] = 0; }
    if (i < BATCH)   { d_gcount[i] = 0; d_gcur[i] = 0; }
    if (i < HID) {
        d_bn1s[i] = 0.f; d_bn1q[i] = 0.f;
        d_bn2s[i] = 0.f; d_bn2q[i] = 0.f;
        d_bn3s[i] = 0.f; d_bn3q[i] = 0.f;
    }
    if (i == 0) d_meanAcc = 0.f;
}

__global__ void k_deg(const int* __restrict__ src, const int* __restrict__ dst) {
    int e = blockIdx.x * blockDim.x + threadIdx.x;
    if (e >= N_EDGES) return;
    int s = src[e], d = dst[e];
    atomicAdd(&d_deg_out[s], 1);
    atomicAdd(&d_deg_in[d], 1);
    atomicAdd(&d_gcount[d / NPG], 1);
}

__global__ void k_node() {
    int i = blockIdx.x * blockDim.x + threadIdx.x;
    if (i >= N_NODES) return;
    int di = d_deg_in[i], dout = d_deg_out[i];
    d_inv_in[i]  = rsqrtf((float)(di   > 1 ? di   : 1));
    d_inv_out[i] = rsqrtf((float)(dout > 1 ? dout : 1));
    d_cls[i] = di < (IND - 1) ? di : (IND - 1);
}

__global__ void k_scan() {
    __shared__ int s[BATCH];
    int t = threadIdx.x;
    if (t < BATCH) s[t] = d_gcount[t];
    __syncthreads();
    for (int o = 1; o < BATCH; o <<= 1) {
        int v = 0;
        if (t < BATCH && t >= o) v = s[t - o];
        __syncthreads();
        if (t < BATCH && t >= o) s[t] += v;
        __syncthreads();
    }
    if (t < BATCH) d_goff[t + 1] = s[t];
    if (t == 0) d_goff[0] = 0;
}

__global__ void k_bucket(const int* __restrict__ dst) {
    int e = blockIdx.x * blockDim.x + threadIdx.x;
    if (e >= N_EDGES) return;
    int g = dst[e] / NPG;
    int p = atomicAdd(&d_gcur[g], 1);
    d_ebuck[d_goff[g] + p] = e;
}

// Per-graph counting sort by local dst -> CSR (d_off, d_esrc)
__global__ void k_sort(const int* __restrict__ src, const int* __restrict__ dst) {
    __shared__ int cnt[NPG];
    __shared__ int cur[NPG + 1];
    int g = blockIdx.x, t = threadIdx.x;
    if (t < NPG) cnt[t] = 0;
    __syncthreads();
    int lo = d_goff[g], hi = d_goff[g + 1];
    for (int p = lo + t; p < hi; p += blockDim.x) {
        int e = d_ebuck[p];
        atomicAdd(&cnt[dst[e] - g * NPG], 1);
    }
    __syncthreads();
    if (t == 0) {
        int run = 0;
        for (int j = 0; j < NPG; j++) { cur[j] = run; run += cnt[j]; }
        cur[NPG] = run;
    }
    __syncthreads();
    if (t < NPG) d_off[g * NPG + t] = lo + cur[t];
    if (g == 0 && t == 0) d_off[N_NODES] = N_EDGES;
    __syncthreads();
    for (int p = lo + t; p < hi; p += blockDim.x) {
        int e = d_ebuck[p];
        int dl = dst[e] - g * NPG;
        int pos = atomicAdd(&cur[dl], 1);
        d_esrc[lo + pos] = src[e];
    }
}

// Layer 1: one-hot gather fused with 20x128 matmul; write pre, accumulate BN stats
#define L1_NODES 16
__global__ void k_layer1(const float* __restrict__ W1, const float* __restrict__ b1) {
    int c = threadIdx.x;
    int base = blockIdx.x * L1_NODES;
    float b1c = b1[c];
    float s1 = 0.f, s2 = 0.f;
    for (int nd = 0; nd < L1_NODES; nd++) {
        int i = base + nd;
        int lo = d_off[i], hi = d_off[i + 1];
        float acc = 0.f;
        for (int e = lo; e < hi; e++) {
            int s = d_esrc[e];
            acc += d_inv_out[s] * W1[d_cls[s] * HID + c];
        }
        float y = acc * d_inv_in[i] + b1c;
        d_pre[i * HID + c] = y;
        s1 += y; s2 += y * y;
    }
    atomicAdd(&d_bn1s[c], s1);
    atomicAdd(&d_bn1q[c], s2);
}

// BN + ELU, layer1 output premultiplied by inv_out
__global__ void k_bnelu1(const float* __restrict__ g1, const float* __restrict__ be1) {
    int idx = blockIdx.x * blockDim.x + threadIdx.x;
    if (idx >= N_NODES * HID) return;
    int c = idx & (HID - 1);
    int i = idx >> 7;
    float inv = 1.f / (float)N_NODES;
    float mu = d_bn1s[c] * inv;
    float var = d_bn1q[c] * inv - mu * mu;
    float rstd = rsqrtf(var + EPS);
    float y = (d_pre[idx] - mu) * rstd * g1[c] + be1[c];
    float h = y > 0.f ? y : expm1f(y);
    d_h1m[idx] = h * d_inv_out[i];
}

// Layer 2: gather + 128x128 matmul fused, 8 nodes per block
#define L2_NODES 8
__global__ void k_layer2(const float* __restrict__ W2, const float* __restrict__ b2) {
    __shared__ float aggS[L2_NODES][HID];
    int c = threadIdx.x;
    int base = blockIdx.x * L2_NODES;
    for (int nd = 0; nd < L2_NODES; nd++) {
        int i = base + nd;
        int lo = d_off[i], hi = d_off[i + 1];
        float acc = 0.f;
        for (int e = lo; e < hi; e++)
            acc += d_h1m[d_esrc[e] * HID + c];
        aggS[nd][c] = acc * d_inv_in[i];
    }
    __syncthreads();
    float acc[L2_NODES];
    float b2c = b2[c];
#pragma unroll
    for (int nd = 0; nd < L2_NODES; nd++) acc[nd] = b2c;
    for (int k = 0; k < HID; k += 4) {
        float w0 = W2[(k + 0) * HID + c];
        float w1 = W2[(k + 1) * HID + c];
        float w2 = W2[(k + 2) * HID + c];
        float w3 = W2[(k + 3) * HID + c];
#pragma unroll
        for (int nd = 0; nd < L2_NODES; nd++) {
            float4 a = *reinterpret_cast<float4*>(&aggS[nd][k]);
            acc[nd] += a.x * w0 + a.y * w1 + a.z * w2 + a.w * w3;
        }
    }
    float s1 = 0.f, s2 = 0.f;
#pragma unroll
    for (int nd = 0; nd < L2_NODES; nd++) {
        float y = acc[nd];
        d_pre[(base + nd) * HID + c] = y;
        s1 += y; s2 += y * y;
    }
    atomicAdd(&d_bn2s[c], s1);
    atomicAdd(&d_bn2q[c], s2);
}

__global__ void k_bnelu2(const float* __restrict__ g2, const float* __restrict__ be2) {
    int idx = blockIdx.x * blockDim.x + threadIdx.x;
    if (idx >= N_NODES * HID) return;
    int c = idx & (HID - 1);
    float inv = 1.f / (float)N_NODES;
    float mu = d_bn2s[c] * inv;
    float var = d_bn2q[c] * inv - mu * mu;
    float rstd = rsqrtf(var + EPS);
    float y = (d_pre[idx] - mu) * rstd * g2[c] + be2[c];
    d_h2[idx] = y > 0.f ? y : expm1f(y);
}

// t[j] = inv_out[j] * dot(h2[j], Wv) ; one warp per node
__global__ void k_tdot(const float* __restrict__ Wv) {
    int gtid = blockIdx.x * blockDim.x + threadIdx.x;
    int j = gtid >> 5;
    int lane = gtid & 31;
    if (j >= N_NODES) return;
    float4 a = reinterpret_cast<const float4*>(d_h2 + j * HID)[lane];
    float4 w = reinterpret_cast<const float4*>(Wv)[lane];
    float s = a.x * w.x + a.y * w.y + a.z * w.z + a.w * w.w;
    for (int o = 16; o > 0; o >>= 1) s += __shfl_xor_sync(0xffffffffu, s, o);
    if (lane == 0) d_t[j] = s * d_inv_out[j];
}

// Per graph: d[i] = inv_in[i]*sum(t[src]) + bv ; vec[g][c] = sum_j d[j]*h2[j][c]
__global__ void k_readout(const float* __restrict__ bv) {
    __shared__ float dS[NPG];
    __shared__ float ws[4];
    int g = blockIdx.x, c = threadIdx.x;
    float bv0 = bv[0];
    if (c < NPG) {
        int i = g * NPG + c;
        int lo = d_off[i], hi = d_off[i + 1];
        float a = 0.f;
        for (int e = lo; e < hi; e++) a += d_t[d_esrc[e]];
        dS[c] = d_inv_in[i] * a + bv0;
    }
    __syncthreads();
    float acc = 0.f;
    const float* h2g = d_h2 + (long)g * NPG * HID;
    for (int j = 0; j < NPG; j++)
        acc += dS[j] * h2g[j * HID + c];
    d_vec[g * HID + c] = acc;
    // block-sum for global mean
    float s = acc;
    for (int o = 16; o > 0; o >>= 1) s += __shfl_xor_sync(0xffffffffu, s, o);
    int lane = c & 31, wid = c >> 5;
    if (lane == 0) ws[wid] = s;
    __syncthreads();
    if (c == 0) atomicAdd(&d_meanAcc, ws[0] + ws[1] + ws[2] + ws[3]);
}

__global__ void k_shrink() {
    int idx = blockIdx.x * blockDim.x + threadIdx.x;
    if (idx >= BATCH * HID) return;
    float mean = d_meanAcc * (1.f / (BATCH * HID));
    float x = d_vec[idx];
    float s = fmaxf(x - mean, 0.f) - fmaxf(-x - mean, 0.f);
    d_hg0[idx] = tanhf(s);
}

// z = hg0 @ Wg + bg, BN3 stats
#define FC_ROWS 8
__global__ void k_fc(const float* __restrict__ Wg, const float* __restrict__ bg) {
    __shared__ float rowS[FC_ROWS][HID];
    int c = threadIdx.x;
    int r0 = blockIdx.x * FC_ROWS;
    for (int nd = 0; nd < FC_ROWS; nd++)
        rowS[nd][c] = d_hg0[(r0 + nd) * HID + c];
    __syncthreads();
    float acc[FC_ROWS];
    float bgc = bg[c];
#pragma unroll
    for (int nd = 0; nd < FC_ROWS; nd++) acc[nd] = bgc;
    for (int k = 0; k < HID; k += 4) {
        float w0 = Wg[(k + 0) * HID + c];
        float w1 = Wg[(k + 1) * HID + c];
        float w2 = Wg[(k + 2) * HID + c];
        float w3 = Wg[(k + 3) * HID + c];
#pragma unroll
        for (int nd = 0; nd < FC_ROWS; nd++) {
            float4 a = *reinterpret_cast<float4*>(&rowS[nd][k]);
            acc[nd] += a.x * w0 + a.y * w1 + a.z * w2 + a.w * w3;
        }
    }
    float s1 = 0.f, s2 = 0.f;
#pragma unroll
    for (int nd = 0; nd < FC_ROWS; nd++) {
        float y = acc[nd];
        d_z[(r0 + nd) * HID + c] = y;
        s1 += y; s2 += y * y;
    }
    atomicAdd(&d_bn3s[c], s1);
    atomicAdd(&d_bn3q[c], s2);
}

// hg2 = tanh(bn(z)); out = tanh(hg2 @ Wc + bc)
__global__ void k_final(const float* __restrict__ g3, const float* __restrict__ be3,
                        const float* __restrict__ Wc, const float* __restrict__ bc,
                        float* __restrict__ out) {
    __shared__ float hs[HID];
    int b = blockIdx.x, c = threadIdx.x;
    float inv = 1.f / (float)BATCH;
    float mu = d_bn3s[c] * inv;
    float var = d_bn3q[c] * inv - mu * mu;
    float rstd = rsqrtf(var + EPS);
    float v = tanhf((d_z[b * HID + c] - mu) * rstd * g3[c] + be3[c]);
    hs[c] = v;
    __syncthreads();
    if (c < NC) {
        float a = bc[c];
        for (int k = 0; k < HID; k++)
            a += hs[k] * Wc[k * NC + c];
        out[b * NC + c] = tanhf(a);
    }
}

// ---------------- launch ----------------
extern "C" void kernel_launch(void* const* d_in, const int* in_sizes, int n_in,
                              void* d_out, int out_size) {
    const int*   src = (const int*)d_in[0];
    const int*   dst = (const int*)d_in[1];
    // d_in[2] = graph_id (== i/100, unused)
    const float* W1  = (const float*)d_in[3];
    const float* b1  = (const float*)d_in[4];
    const float* g1  = (const float*)d_in[5];
    const float* be1 = (const float*)d_in[6];
    const float* W2  = (const float*)d_in[7];
    const float* b2  = (const float*)d_in[8];
    const float* g2  = (const float*)d_in[9];
    const float* be2 = (const float*)d_in[10];
    const float* Wv  = (const float*)d_in[11];
    const float* bv  = (const float*)d_in[12];
    // d_in[13] = Wd, d_in[14] = bd : unused by reference
    const float* Wg  = (const float*)d_in[15];
    const float* bg  = (const float*)d_in[16];
    const float* g3  = (const float*)d_in[17];
    const float* be3 = (const float*)d_in[18];
    const float* Wc  = (const float*)d_in[19];
    const float* bc  = (const float*)d_in[20];
    float* out = (float*)d_out;

    k_zero<<<(N_NODES + 255) / 256, 256>>>();
    k_deg<<<(N_EDGES + 255) / 256, 256>>>(src, dst);
    k_node<<<(N_NODES + 255) / 256, 256>>>();
    k_scan<<<1, 1024>>>();
    k_bucket<<<(N_EDGES + 255) / 256, 256>>>(dst);
    k_sort<<<BATCH, 128>>>(src, dst);
    k_layer1<<<N_NODES / L1_NODES, HID>>>(W1, b1);
    k_bnelu1<<<(N_NODES * HID + 255) / 256, 256>>>(g1, be1);
    k_layer2<<<N_NODES / L2_NODES, HID>>>(W2, b2);
    k_bnelu2<<<(N_NODES * HID + 255) / 256, 256>>>(g2, be2);
    k_tdot<<<(N_NODES * 32 + 255) / 256, 256>>>(Wv);
    k_readout<<<BATCH, HID>>>(bv);
    k_shrink<<<(BATCH * HID + 255) / 256, 256>>>();
    k_fc<<<BATCH / FC_ROWS, HID>>>(Wg, bg);
    k_final<<<BATCH, HID>>>(g3, be3, Wc, bc, out);
}

// round 5
// speedup vs baseline: 1.1947x; 1.1947x over previous
#include <cuda_runtime.h>
#include <cuda_bf16.h>
#include <math.h>

#define N_NODES 80000
#define N_EDGES 640000
#define BATCH   800
#define NPG     100
#define HID     128
#define NC      10
#define IND     20
#define EPS     1e-5f
#define ECAP    1280

// ---------------- scratch ----------------
__device__ int    d_deg_in[N_NODES];
__device__ int    d_deg_out[N_NODES];
__device__ float  d_inv_in[N_NODES];
__device__ float  d_inv_out[N_NODES];
__device__ float2 d_ninfo[N_NODES];           // (inv_out, cls)

__device__ int   d_gcount[BATCH];
__device__ int   d_gcur[BATCH];
__device__ int   d_goff[BATCH + 1];
__device__ int   d_ebuck[N_EDGES];            // packed (src<<7)|dst_local
__device__ int   d_esrc[N_EDGES];             // LOCAL src id, CSR by dst
__device__ int   d_off[N_NODES + 1];

__device__ float d_acc20[N_NODES * IND];

__device__ float d_pre[N_NODES * HID];        // pre1 then pre2
__device__ float d_h2[N_NODES * HID];
__device__ float d_t[N_NODES];
__device__ float d_vec[BATCH * HID];
__device__ float d_z[BATCH * HID];

__device__ float d_bn1s[HID], d_bn1q[HID];
__device__ float d_bn2s[HID], d_bn2q[HID];
__device__ float d_bn3s[HID], d_bn3q[HID];
__device__ float d_meanAcc;

__device__ __forceinline__ unsigned f2tf32(float x) {
    unsigned r; asm("cvt.rna.tf32.f32 %0, %1;" : "=r"(r) : "f"(x)); return r;
}
// split fp32 into tf32 hi + tf32 lo (3xTF32 trick)
__device__ __forceinline__ void tf32split(float x, unsigned& hi, unsigned& lo) {
    hi = f2tf32(x);
    lo = f2tf32(x - __uint_as_float(hi));
}
__device__ __forceinline__ float fast_elu(float y) {
    return y > 0.f ? y : (__expf(y) - 1.0f);
}

// ---------------- kernels ----------------

__global__ void k_zero() {
    int i = blockIdx.x * blockDim.x + threadIdx.x;   // grid covers 1.6M
    if (i < N_NODES * IND) d_acc20[i] = 0.f;
    if (i < N_NODES) { d_deg_in[i] = 0; d_deg_out[i] = 0; }
    if (i < BATCH)   { d_gcount[i] = 0; d_gcur[i] = 0; }
    if (i < HID) {
        d_bn1s[i] = 0.f; d_bn1q[i] = 0.f;
        d_bn2s[i] = 0.f; d_bn2q[i] = 0.f;
        d_bn3s[i] = 0.f; d_bn3q[i] = 0.f;
    }
    if (i == 0) d_meanAcc = 0.f;
}

__global__ void k_deg(const int* __restrict__ src, const int* __restrict__ dst) {
    int e = blockIdx.x * blockDim.x + threadIdx.x;
    if (e >= N_EDGES) return;
    int s = src[e], d = dst[e];
    atomicAdd(&d_deg_out[s], 1);
    atomicAdd(&d_deg_in[d], 1);
    atomicAdd(&d_gcount[d / NPG], 1);
}

__global__ void k_node() {
    int i = blockIdx.x * blockDim.x + threadIdx.x;
    if (i >= N_NODES) return;
    int di = d_deg_in[i], dout = d_deg_out[i];
    float ii = rsqrtf((float)(di   > 1 ? di   : 1));
    float io = rsqrtf((float)(dout > 1 ? dout : 1));
    d_inv_in[i] = ii;
    d_inv_out[i] = io;
    int cls = di < (IND - 1) ? di : (IND - 1);
    d_ninfo[i] = make_float2(io, (float)cls);
}

__global__ void k_scan() {
    __shared__ int s[BATCH];
    int t = threadIdx.x;
    if (t < BATCH) s[t] = d_gcount[t];
    __syncthreads();
    for (int o = 1; o < BATCH; o <<= 1) {
        int v = 0;
        if (t < BATCH && t >= o) v = s[t - o];
        __syncthreads();
        if (t < BATCH && t >= o) s[t] += v;
        __syncthreads();
    }
    if (t < BATCH) d_goff[t + 1] = s[t];
    if (t == 0) d_goff[0] = 0;
}

// bucket (packed) + 20-class scatter in one edge pass
__global__ void k_bucketscat(const int* __restrict__ src, const int* __restrict__ dst) {
    int e = blockIdx.x * blockDim.x + threadIdx.x;
    if (e >= N_EDGES) return;
    int s = src[e], d = dst[e];
    int g = d / NPG;
    int p = atomicAdd(&d_gcur[g], 1);
    d_ebuck[d_goff[g] + p] = (s << 7) | (d - g * NPG);
    float2 ni = d_ninfo[s];
    atomicAdd(&d_acc20[d * IND + (int)ni.y], ni.x);
}

// per-graph counting sort by local dst -> CSR with LOCAL src ids
__global__ void k_sort() {
    __shared__ int cnt[NPG];
    __shared__ int cur[NPG + 1];
    int g = blockIdx.x, t = threadIdx.x;
    if (t < NPG) cnt[t] = 0;
    __syncthreads();
    int lo = d_goff[g], hi = d_goff[g + 1];
    for (int p = lo + t; p < hi; p += blockDim.x)
        atomicAdd(&cnt[d_ebuck[p] & 127], 1);
    __syncthreads();
    if (t == 0) {
        int run = 0;
        for (int j = 0; j < NPG; j++) { cur[j] = run; run += cnt[j]; }
        cur[NPG] = run;
    }
    __syncthreads();
    if (t < NPG) d_off[g * NPG + t] = lo + cur[t];
    if (g == 0 && t == 0) d_off[N_NODES] = N_EDGES;
    __syncthreads();
    for (int p = lo + t; p < hi; p += blockDim.x) {
        int v = d_ebuck[p];
        int pos = atomicAdd(&cur[v & 127], 1);
        d_esrc[lo + pos] = (v >> 7) - g * NPG;   // local src
    }
}

// pre1 = (acc20 * inv_in) @ W1 + b1 ; bn1 stats
#define L1N 64
__global__ void k_l1gemm(const float* __restrict__ W1, const float* __restrict__ b1) {
    __shared__ float a20[L1N * IND];
    __shared__ float invs[L1N];
    int c = threadIdx.x;
    int base = blockIdx.x * L1N;
    for (int idx = c; idx < L1N * IND; idx += HID)
        a20[idx] = d_acc20[base * IND + idx];
    if (c < L1N) invs[c] = d_inv_in[base + c];
    float w1r[IND];
#pragma unroll
    for (int k = 0; k < IND; k++) w1r[k] = W1[k * HID + c];
    float b1c = b1[c];
    __syncthreads();
    float s1 = 0.f, s2 = 0.f;
    for (int nd = 0; nd < L1N; nd++) {
        float acc = 0.f;
#pragma unroll
        for (int k = 0; k < IND; k++) acc += a20[nd * IND + k] * w1r[k];
        float y = acc * invs[nd] + b1c;
        d_pre[(base + nd) * HID + c] = y;
        s1 += y; s2 += y * y;
    }
    atomicAdd(&d_bn1s[c], s1);
    atomicAdd(&d_bn1q[c], s2);
}

// ---------- layer 2: persistent, per-graph smem staging + 3xTF32 MMA ----------
#define L2T 512
__global__ __launch_bounds__(L2T, 1)
void k_layer2(const float* __restrict__ g1, const float* __restrict__ be1,
              const float* __restrict__ W2, const float* __restrict__ b2) {
    extern __shared__ float smem[];
    float*    W2s    = smem;                       // 128*136 fp32
    float*    aggf   = W2s + 128 * 136;            // 112*132 fp32
    float*    h1m    = aggf + 112 * 132;           // 100*128
    float*    alpha  = h1m + 100 * 128;            // 128
    float*    beta   = alpha + 128;                // 128
    float*    b2s    = beta + 128;                 // 128
    float*    invin  = b2s + 128;                  // 104
    int*      off_s  = (int*)(invin + 104);        // 104
    int*      esrc_s = off_s + 104;                // ECAP

    int tid = threadIdx.x;
    int wp = tid >> 5, lane = tid & 31;

    // one-time init: W2 fp32 into smem (padded stride 136)
    for (int idx = tid; idx < HID * HID; idx += L2T) {
        int k = idx >> 7, n = idx & 127;
        W2s[k * 136 + n] = W2[idx];
    }
    if (tid < HID) {
        float invN = 1.f / (float)N_NODES;
        float mu = d_bn1s[tid] * invN;
        float var = d_bn1q[tid] * invN - mu * mu;
        float rstd = rsqrtf(var + EPS);
        float a = g1[tid] * rstd;
        alpha[tid] = a;
        beta[tid] = be1[tid] - mu * a;
        b2s[tid] = b2[tid];
    }
    for (int idx = tid; idx < 12 * 132; idx += L2T)
        aggf[100 * 132 + idx] = 0.f;               // zero pad rows 100..111
    __syncthreads();

    for (int g = blockIdx.x; g < BATCH; g += gridDim.x) {
        // phase a: load pre1 slice, apply bn1+elu, * inv_out -> h1m smem
        const float4* P = (const float4*)(d_pre + (long)g * NPG * HID);
        for (int idx = tid; idx < NPG * 32; idx += L2T) {
            float4 v = P[idx];
            int li = idx >> 5;
            int c4 = (idx & 31) * 4;
            float io = d_inv_out[g * NPG + li];
            float4 al = *(const float4*)&alpha[c4];
            float4 be = *(const float4*)&beta[c4];
            v.x = fast_elu(v.x * al.x + be.x) * io;
            v.y = fast_elu(v.y * al.y + be.y) * io;
            v.z = fast_elu(v.z * al.z + be.z) * io;
            v.w = fast_elu(v.w * al.w + be.w) * io;
            ((float4*)h1m)[idx] = v;
        }
        if (tid <= NPG) off_s[tid] = d_off[g * NPG + tid];
        if (tid < NPG) invin[tid] = d_inv_in[g * NPG + tid];
        int eB = d_off[g * NPG];
        int eE = d_off[g * NPG + NPG];
        int cnt = eE - eB;
        for (int idx = tid; idx < cnt && idx < ECAP; idx += L2T)
            esrc_s[idx] = d_esrc[eB + idx];
        __syncthreads();

        // phase b: aggregation (warp per node, float4 channels) -> fp32 agg
        if (cnt <= ECAP) {
            for (int li = wp; li < NPG; li += 16) {
                int lo = off_s[li], hi = off_s[li + 1];
                float4 acc = make_float4(0.f, 0.f, 0.f, 0.f);
                for (int e = lo; e < hi; e++) {
                    int sl = esrc_s[e - eB];
                    float4 v = ((const float4*)h1m)[sl * 32 + lane];
                    acc.x += v.x; acc.y += v.y; acc.z += v.z; acc.w += v.w;
                }
                float ii = invin[li];
                float4 o = make_float4(acc.x * ii, acc.y * ii, acc.z * ii, acc.w * ii);
                *(float4*)&aggf[li * 132 + lane * 4] = o;
            }
        } else {
            for (int li = wp; li < NPG; li += 16) {
                int lo = off_s[li], hi = off_s[li + 1];
                float4 acc = make_float4(0.f, 0.f, 0.f, 0.f);
                for (int e = lo; e < hi; e++) {
                    int sl = d_esrc[e];
                    float4 v = ((const float4*)h1m)[sl * 32 + lane];
                    acc.x += v.x; acc.y += v.y; acc.z += v.z; acc.w += v.w;
                }
                float ii = invin[li];
                float4 o = make_float4(acc.x * ii, acc.y * ii, acc.z * ii, acc.w * ii);
                *(float4*)&aggf[li * 132 + lane * 4] = o;
            }
        }
        __syncthreads();

        // phase c: 3xTF32 MMA — 14 warps: (mtile 0..6) x (nhalf 0..1)
        if (wp < 14) {
            int mt = wp >> 1, nh = wp & 1;
            int row = mt * 16 + (lane >> 2);
            int kk = lane & 3;
            float acc[8][4];
#pragma unroll
            for (int nt = 0; nt < 8; nt++)
#pragma unroll
                for (int q = 0; q < 4; q++) acc[nt][q] = 0.f;
#pragma unroll
            for (int k0 = 0; k0 < HID; k0 += 8) {
                float af0 = aggf[row * 132 + k0 + kk];
                float af1 = aggf[(row + 8) * 132 + k0 + kk];
                float af2 = aggf[row * 132 + k0 + kk + 4];
                float af3 = aggf[(row + 8) * 132 + k0 + kk + 4];
                unsigned ah0, al0, ah1, al1, ah2, al2, ah3, al3;
                tf32split(af0, ah0, al0);
                tf32split(af1, ah1, al1);
                tf32split(af2, ah2, al2);
                tf32split(af3, ah3, al3);
#pragma unroll
                for (int nt = 0; nt < 8; nt++) {
                    int ncol = nh * 64 + nt * 8 + (lane >> 2);
                    float bf0 = W2s[(k0 + kk) * 136 + ncol];
                    float bf1 = W2s[(k0 + kk + 4) * 136 + ncol];
                    unsigned bh0, bl0, bh1, bl1;
                    tf32split(bf0, bh0, bl0);
                    tf32split(bf1, bh1, bl1);
                    // hi*hi
                    asm volatile(
                        "mma.sync.aligned.m16n8k8.row.col.f32.tf32.tf32.f32 "
                        "{%0,%1,%2,%3}, {%4,%5,%6,%7}, {%8,%9}, {%0,%1,%2,%3};"
                        : "+f"(acc[nt][0]), "+f"(acc[nt][1]),
                          "+f"(acc[nt][2]), "+f"(acc[nt][3])
                        : "r"(ah0), "r"(ah1), "r"(ah2), "r"(ah3), "r"(bh0), "r"(bh1));
                    // lo*hi
                    asm volatile(
                        "mma.sync.aligned.m16n8k8.row.col.f32.tf32.tf32.f32 "
                        "{%0,%1,%2,%3}, {%4,%5,%6,%7}, {%8,%9}, {%0,%1,%2,%3};"
                        : "+f"(acc[nt][0]), "+f"(acc[nt][1]),
                          "+f"(acc[nt][2]), "+f"(acc[nt][3])
                        : "r"(al0), "r"(al1), "r"(al2), "r"(al3), "r"(bh0), "r"(bh1));
                    // hi*lo
                    asm volatile(
                        "mma.sync.aligned.m16n8k8.row.col.f32.tf32.tf32.f32 "
                        "{%0,%1,%2,%3}, {%4,%5,%6,%7}, {%8,%9}, {%0,%1,%2,%3};"
                        : "+f"(acc[nt][0]), "+f"(acc[nt][1]),
                          "+f"(acc[nt][2]), "+f"(acc[nt][3])
                        : "r"(ah0), "r"(ah1), "r"(ah2), "r"(ah3), "r"(bl0), "r"(bl1));
                }
            }
            long gi0 = ((long)g * NPG + row) * HID;
            long gi1 = ((long)g * NPG + row + 8) * HID;
#pragma unroll
            for (int nt = 0; nt < 8; nt++) {
                int c0 = nh * 64 + nt * 8 + 2 * (lane & 3);
                float bx = b2s[c0], by = b2s[c0 + 1];
                if (row < NPG)
                    *(float2*)&d_pre[gi0 + c0] = make_float2(acc[nt][0] + bx, acc[nt][1] + by);
                if (row + 8 < NPG)
                    *(float2*)&d_pre[gi1 + c0] = make_float2(acc[nt][2] + bx, acc[nt][3] + by);
            }
        }
        __syncthreads();
    }
}

__global__ void k_bn2stats() {
    int c = threadIdx.x;
    float s = 0.f, q = 0.f;
    for (int r = blockIdx.x; r < N_NODES; r += gridDim.x) {
        float v = d_pre[r * HID + c];
        s += v; q += v * v;
    }
    atomicAdd(&d_bn2s[c], s);
    atomicAdd(&d_bn2q[c], q);
}

// bn2 + elu -> h2 ; t = inv_out * (h2 . Wv)   (warp per node)
__global__ void k_bnelu2td(const float* __restrict__ g2, const float* __restrict__ be2,
                           const float* __restrict__ Wv) {
    int wid = threadIdx.x >> 5, lane = threadIdx.x & 31;
    int j = blockIdx.x * 8 + wid;
    float4 p  = ((const float4*)d_pre)[j * 32 + lane];
    float4 s4 = ((const float4*)d_bn2s)[lane];
    float4 q4 = ((const float4*)d_bn2q)[lane];
    float4 g4 = ((const float4*)g2)[lane];
    float4 b4 = ((const float4*)be2)[lane];
    float4 w4 = ((const float4*)Wv)[lane];
    float invN = 1.f / (float)N_NODES;
    float4 h;
    {
        float mu = s4.x * invN, var = q4.x * invN - mu * mu;
        h.x = fast_elu((p.x - mu) * rsqrtf(var + EPS) * g4.x + b4.x);
        mu = s4.y * invN; var = q4.y * invN - mu * mu;
        h.y = fast_elu((p.y - mu) * rsqrtf(var + EPS) * g4.y + b4.y);
        mu = s4.z * invN; var = q4.z * invN - mu * mu;
        h.z = fast_elu((p.z - mu) * rsqrtf(var + EPS) * g4.z + b4.z);
        mu = s4.w * invN; var = q4.w * invN - mu * mu;
        h.w = fast_elu((p.w - mu) * rsqrtf(var + EPS) * g4.w + b4.w);
    }
    ((float4*)d_h2)[j * 32 + lane] = h;
    float s = h.x * w4.x + h.y * w4.y + h.z * w4.z + h.w * w4.w;
    for (int o = 16; o > 0; o >>= 1) s += __shfl_xor_sync(0xffffffffu, s, o);
    if (lane == 0) d_t[j] = s * d_inv_out[j];
}

__global__ void k_readout(const float* __restrict__ bv) {
    __shared__ float dS[NPG];
    __shared__ float ws[4];
    int g = blockIdx.x, c = threadIdx.x;
    float bv0 = bv[0];
    if (c < NPG) {
        int i = g * NPG + c;
        int lo = d_off[i], hi = d_off[i + 1];
        float a = 0.f;
        for (int e = lo; e < hi; e++) a += d_t[g * NPG + d_esrc[e]];
        dS[c] = d_inv_in[i] * a + bv0;
    }
    __syncthreads();
    float acc = 0.f;
    const float* h2g = d_h2 + (long)g * NPG * HID;
    for (int j = 0; j < NPG; j++)
        acc += dS[j] * h2g[j * HID + c];
    d_vec[g * HID + c] = acc;
    float s = acc;
    for (int o = 16; o > 0; o >>= 1) s += __shfl_xor_sync(0xffffffffu, s, o);
    int lane = c & 31, wid = c >> 5;
    if (lane == 0) ws[wid] = s;
    __syncthreads();
    if (c == 0) atomicAdd(&d_meanAcc, ws[0] + ws[1] + ws[2] + ws[3]);
}

// shrink+tanh fused into FC: z = tanh(shrink(vec)) @ Wg + bg ; bn3 stats
#define FCR 8
__global__ void k_fc(const float* __restrict__ Wg, const float* __restrict__ bg) {
    __shared__ float rowS[FCR][HID];
    int c = threadIdx.x;
    int r0 = blockIdx.x * FCR;
    float mean = d_meanAcc * (1.f / (BATCH * HID));
    for (int nd = 0; nd < FCR; nd++) {
        float x = d_vec[(r0 + nd) * HID + c];
        float sv = fmaxf(x - mean, 0.f) - fmaxf(-x - mean, 0.f);
        rowS[nd][c] = tanhf(sv);
    }
    __syncthreads();
    float acc[FCR];
    float bgc = bg[c];
#pragma unroll
    for (int nd = 0; nd < FCR; nd++) acc[nd] = bgc;
    for (int k = 0; k < HID; k += 4) {
        float w0 = Wg[(k + 0) * HID + c];
        float w1 = Wg[(k + 1) * HID + c];
        float w2 = Wg[(k + 2) * HID + c];
        float w3 = Wg[(k + 3) * HID + c];
#pragma unroll
        for (int nd = 0; nd < FCR; nd++) {
            float4 a = *reinterpret_cast<float4*>(&rowS[nd][k]);
            acc[nd] += a.x * w0 + a.y * w1 + a.z * w2 + a.w * w3;
        }
    }
    float s1 = 0.f, s2 = 0.f;
#pragma unroll
    for (int nd = 0; nd < FCR; nd++) {
        float y = acc[nd];
        d_z[(r0 + nd) * HID + c] = y;
        s1 += y; s2 += y * y;
    }
    atomicAdd(&d_bn3s[c], s1);
    atomicAdd(&d_bn3q[c], s2);
}

__global__ void k_final(const float* __restrict__ g3, const float* __restrict__ be3,
                        const float* __restrict__ Wc, const float* __restrict__ bc,
                        float* __restrict__ out) {
    __shared__ float hs[HID];
    int b = blockIdx.x, c = threadIdx.x;
    float inv = 1.f / (float)BATCH;
    float mu = d_bn3s[c] * inv;
    float var = d_bn3q[c] * inv - mu * mu;
    float rstd = rsqrtf(var + EPS);
    float v = tanhf((d_z[b * HID + c] - mu) * rstd * g3[c] + be3[c]);
    hs[c] = v;
    __syncthreads();
    if (c < NC) {
        float a = bc[c];
        for (int k = 0; k < HID; k++)
            a += hs[k] * Wc[k * NC + c];
        out[b * NC + c] = tanhf(a);
    }
}

// ---------------- launch ----------------
extern "C" void kernel_launch(void* const* d_in, const int* in_sizes, int n_in,
                              void* d_out, int out_size) {
    const int*   src = (const int*)d_in[0];
    const int*   dst = (const int*)d_in[1];
    const float* W1  = (const float*)d_in[3];
    const float* b1  = (const float*)d_in[4];
    const float* g1  = (const float*)d_in[5];
    const float* be1 = (const float*)d_in[6];
    const float* W2  = (const float*)d_in[7];
    const float* b2  = (const float*)d_in[8];
    const float* g2  = (const float*)d_in[9];
    const float* be2 = (const float*)d_in[10];
    const float* Wv  = (const float*)d_in[11];
    const float* bv  = (const float*)d_in[12];
    const float* Wg  = (const float*)d_in[15];
    const float* bg  = (const float*)d_in[16];
    const float* g3  = (const float*)d_in[17];
    const float* be3 = (const float*)d_in[18];
    const float* Wc  = (const float*)d_in[19];
    const float* bc  = (const float*)d_in[20];
    float* out = (float*)d_out;

    static int smem_set = 0;
    const int L2_SMEM = (128 * 136 + 112 * 132 + 100 * 128 + 3 * 128 + 104) * 4
                        + 104 * 4 + ECAP * 4;
    if (!smem_set) {
        cudaFuncSetAttribute(k_layer2, cudaFuncAttributeMaxDynamicSharedMemorySize, L2_SMEM);
        smem_set = 1;
    }

    k_zero<<<(N_NODES * IND + 255) / 256, 256>>>();
    k_deg<<<(N_EDGES + 255) / 256, 256>>>(src, dst);
    k_node<<<(N_NODES + 255) / 256, 256>>>();
    k_scan<<<1, 1024>>>();
    k_bucketscat<<<(N_EDGES + 255) / 256, 256>>>(src, dst);
    k_sort<<<BATCH, 128>>>();
    k_l1gemm<<<N_NODES / L1N, HID>>>(W1, b1);
    k_layer2<<<148, L2T, L2_SMEM>>>(g1, be1, W2, b2);
    k_bn2stats<<<400, HID>>>();
    k_bnelu2td<<<N_NODES / 8, 256>>>(g2, be2, Wv);
    k_readout<<<BATCH, HID>>>(bv);
    k_fc<<<BATCH / FCR, HID>>>(Wg, bg);
    k_final<<<BATCH, HID>>>(g3, be3, Wc, bc, out);
}

// round 6
// speedup vs baseline: 1.2277x; 1.0276x over previous
#include <cuda_runtime.h>
#include <cuda_bf16.h>
#include <math.h>

#define N_NODES 80000
#define N_EDGES 640000
#define BATCH   800
#define NPG     100
#define HID     128
#define NC      10
#define IND     20
#define EPS     1e-5f
#define ECAP    1280

// ---------------- scratch ----------------
__device__ int    d_deg_in[N_NODES];
__device__ int    d_deg_out[N_NODES];
__device__ float  d_inv_in[N_NODES];
__device__ float  d_inv_out[N_NODES];
__device__ float2 d_ninfo[N_NODES];           // (inv_out, cls)

__device__ int   d_gcount[BATCH];
__device__ int   d_gcur[BATCH];
__device__ int   d_goff[BATCH + 1];
__device__ int   d_ebuck[N_EDGES];            // packed (src<<7)|dst_local
__device__ int   d_esrc[N_EDGES];             // LOCAL src id, CSR by dst
__device__ int   d_off[N_NODES + 1];

__device__ float d_acc20[N_NODES * IND];

__device__ float d_pre[N_NODES * HID];        // pre2 only
__device__ float d_vec[BATCH * HID];
__device__ float d_z[BATCH * HID];

__device__ float d_bn1s[HID], d_bn1q[HID];
__device__ float d_bn2s[HID], d_bn2q[HID];
__device__ float d_bn3s[HID], d_bn3q[HID];
__device__ float d_meanAcc;

__device__ __forceinline__ unsigned f2tf32(float x) {
    unsigned r; asm("cvt.rna.tf32.f32 %0, %1;" : "=r"(r) : "f"(x)); return r;
}
__device__ __forceinline__ void tf32split(float x, unsigned& hi, unsigned& lo) {
    hi = f2tf32(x);
    lo = f2tf32(x - __uint_as_float(hi));
}
__device__ __forceinline__ float fast_elu(float y) {
    return y > 0.f ? y : (__expf(y) - 1.0f);
}

// ---------------- kernels ----------------

__global__ void k_zero() {
    int i = blockIdx.x * blockDim.x + threadIdx.x;   // grid covers 1.6M
    if (i < N_NODES * IND) d_acc20[i] = 0.f;
    if (i < N_NODES) { d_deg_in[i] = 0; d_deg_out[i] = 0; }
    if (i < BATCH)   { d_gcount[i] = 0; d_gcur[i] = 0; }
    if (i < HID) {
        d_bn1s[i] = 0.f; d_bn1q[i] = 0.f;
        d_bn2s[i] = 0.f; d_bn2q[i] = 0.f;
        d_bn3s[i] = 0.f; d_bn3q[i] = 0.f;
    }
    if (i == 0) d_meanAcc = 0.f;
}

__global__ void k_deg(const int* __restrict__ src, const int* __restrict__ dst) {
    int e = blockIdx.x * blockDim.x + threadIdx.x;
    if (e >= N_EDGES) return;
    int s = src[e], d = dst[e];
    atomicAdd(&d_deg_out[s], 1);
    atomicAdd(&d_deg_in[d], 1);
    atomicAdd(&d_gcount[d / NPG], 1);
}

// node info (blocks 0..78) + batch prefix scan (block 79)
__global__ void k_nodescan() {
    if (blockIdx.x < 79) {
        int i = blockIdx.x * 1024 + threadIdx.x;
        if (i >= N_NODES) return;
        int di = d_deg_in[i], dout = d_deg_out[i];
        float ii = rsqrtf((float)(di   > 1 ? di   : 1));
        float io = rsqrtf((float)(dout > 1 ? dout : 1));
        d_inv_in[i] = ii;
        d_inv_out[i] = io;
        int cls = di < (IND - 1) ? di : (IND - 1);
        d_ninfo[i] = make_float2(io, (float)cls);
    } else {
        __shared__ int s[BATCH];
        int t = threadIdx.x;
        if (t < BATCH) s[t] = d_gcount[t];
        __syncthreads();
        for (int o = 1; o < BATCH; o <<= 1) {
            int v = 0;
            if (t < BATCH && t >= o) v = s[t - o];
            __syncthreads();
            if (t < BATCH && t >= o) s[t] += v;
            __syncthreads();
        }
        if (t < BATCH) d_goff[t + 1] = s[t];
        if (t == 0) d_goff[0] = 0;
    }
}

// bucket (packed) + 20-class scatter in one edge pass
__global__ void k_bucketscat(const int* __restrict__ src, const int* __restrict__ dst) {
    int e = blockIdx.x * blockDim.x + threadIdx.x;
    if (e >= N_EDGES) return;
    int s = src[e], d = dst[e];
    int g = d / NPG;
    int p = atomicAdd(&d_gcur[g], 1);
    d_ebuck[d_goff[g] + p] = (s << 7) | (d - g * NPG);
    float2 ni = d_ninfo[s];
    atomicAdd(&d_acc20[d * IND + (int)ni.y], ni.x);
}

// per-graph counting sort by local dst -> CSR with LOCAL src ids
__global__ void k_sort() {
    __shared__ int cnt[NPG];
    __shared__ int cur[NPG + 1];
    int g = blockIdx.x, t = threadIdx.x;
    if (t < NPG) cnt[t] = 0;
    __syncthreads();
    int lo = d_goff[g], hi = d_goff[g + 1];
    for (int p = lo + t; p < hi; p += blockDim.x)
        atomicAdd(&cnt[d_ebuck[p] & 127], 1);
    __syncthreads();
    if (t == 0) {
        int run = 0;
        for (int j = 0; j < NPG; j++) { cur[j] = run; run += cnt[j]; }
        cur[NPG] = run;
    }
    __syncthreads();
    if (t < NPG) d_off[g * NPG + t] = lo + cur[t];
    if (g == 0 && t == 0) d_off[N_NODES] = N_EDGES;
    __syncthreads();
    for (int p = lo + t; p < hi; p += blockDim.x) {
        int v = d_ebuck[p];
        int pos = atomicAdd(&cur[v & 127], 1);
        d_esrc[lo + pos] = (v >> 7) - g * NPG;   // local src
    }
}

// bn1 stats only (pre1 never stored)
#define L1N 64
__global__ void k_l1stats(const float* __restrict__ W1, const float* __restrict__ b1) {
    __shared__ float a20[L1N * IND];
    __shared__ float invs[L1N];
    int c = threadIdx.x;
    int base = blockIdx.x * L1N;
    for (int idx = c; idx < L1N * IND; idx += HID)
        a20[idx] = d_acc20[base * IND + idx];
    if (c < L1N) invs[c] = d_inv_in[base + c];
    float w1r[IND];
#pragma unroll
    for (int k = 0; k < IND; k++) w1r[k] = W1[k * HID + c];
    float b1c = b1[c];
    __syncthreads();
    float s1 = 0.f, s2 = 0.f;
    for (int nd = 0; nd < L1N; nd++) {
        float acc = 0.f;
#pragma unroll
        for (int k = 0; k < IND; k++) acc += a20[nd * IND + k] * w1r[k];
        float y = acc * invs[nd] + b1c;
        s1 += y; s2 += y * y;
    }
    atomicAdd(&d_bn1s[c], s1);
    atomicAdd(&d_bn1q[c], s2);
}

// ---------- layer 2: persistent; recompute pre1 from acc20, agg, 3xTF32 MMA ----------
#define L2T 512
__global__ __launch_bounds__(L2T, 1)
void k_layer2(const float* __restrict__ g1, const float* __restrict__ be1,
              const float* __restrict__ W1, const float* __restrict__ b1,
              const float* __restrict__ W2, const float* __restrict__ b2) {
    extern __shared__ float smem[];
    float*    W2s    = smem;                       // 128*136
    float*    aggf   = W2s + 128 * 136;            // 112*132
    float*    h1m    = aggf + 112 * 132;           // 100*128
    float*    W1s    = h1m + 100 * 128;            // 20*128
    float*    a20s   = W1s + 20 * 128;             // 100*20
    float*    alpha  = a20s + 100 * IND;           // 128 (bn1 scale)
    float*    beta1p = alpha + 128;                // 128 (alpha*b1 + beta)
    float*    b2s    = beta1p + 128;               // 128
    float*    invin  = b2s + 128;                  // 100
    float*    invout = invin + 100;                // 100
    int*      off_s  = (int*)(invout + 100);       // 104
    int*      esrc_s = off_s + 104;                // ECAP

    int tid = threadIdx.x;
    int wp = tid >> 5, lane = tid & 31;

    // one-time init
    for (int idx = tid; idx < HID * HID; idx += L2T) {
        int k = idx >> 7, n = idx & 127;
        W2s[k * 136 + n] = W2[idx];
    }
    for (int idx = tid; idx < IND * HID; idx += L2T)
        W1s[idx] = W1[idx];
    if (tid < HID) {
        float invN = 1.f / (float)N_NODES;
        float mu = d_bn1s[tid] * invN;
        float var = d_bn1q[tid] * invN - mu * mu;
        float rstd = rsqrtf(var + EPS);
        float a = g1[tid] * rstd;
        alpha[tid] = a;
        beta1p[tid] = a * b1[tid] + (be1[tid] - mu * a);
        b2s[tid] = b2[tid];
    }
    for (int idx = tid; idx < 12 * 132; idx += L2T)
        aggf[100 * 132 + idx] = 0.f;               // zero pad rows 100..111
    __syncthreads();

    // per-thread persistent W1 column + bn consts
    int cc = tid & 127;
    int grp = tid >> 7;                            // 0..3 -> li block of 25
    float w1c[IND];
#pragma unroll
    for (int k = 0; k < IND; k++) w1c[k] = W1s[k * HID + cc];
    float alpha_c = alpha[cc], beta_c = beta1p[cc];

    for (int g = blockIdx.x; g < BATCH; g += gridDim.x) {
        // phase 0: stage per-graph data
        for (int idx = tid; idx < NPG * IND; idx += L2T)
            a20s[idx] = d_acc20[g * NPG * IND + idx];
        if (tid < NPG) {
            invin[tid]  = d_inv_in[g * NPG + tid];
            invout[tid] = d_inv_out[g * NPG + tid];
        }
        if (tid >= 128 && tid - 128 <= NPG) off_s[tid - 128] = d_off[g * NPG + tid - 128];
        int eB = d_off[g * NPG];
        int eE = d_off[g * NPG + NPG];
        int cnt = eE - eB;
        for (int idx = tid; idx < cnt && idx < ECAP; idx += L2T)
            esrc_s[idx] = d_esrc[eB + idx];
        __syncthreads();

        // phase a: recompute pre1 -> bn1 -> elu -> *inv_out -> h1m
        for (int li = grp * 25; li < grp * 25 + 25; li++) {
            float acc = 0.f;
#pragma unroll
            for (int k = 0; k < IND; k++) acc += a20s[li * IND + k] * w1c[k];
            float h = fast_elu(acc * (alpha_c * invin[li]) + beta_c) * invout[li];
            h1m[li * HID + cc] = h;
        }
        __syncthreads();

        // phase b: aggregation (warp per node, float4 channels)
        if (cnt <= ECAP) {
            for (int li = wp; li < NPG; li += 16) {
                int lo = off_s[li], hi = off_s[li + 1];
                float4 acc = make_float4(0.f, 0.f, 0.f, 0.f);
                for (int e = lo; e < hi; e++) {
                    int sl = esrc_s[e - eB];
                    float4 v = ((const float4*)h1m)[sl * 32 + lane];
                    acc.x += v.x; acc.y += v.y; acc.z += v.z; acc.w += v.w;
                }
                float ii = invin[li];
                float4 o = make_float4(acc.x * ii, acc.y * ii, acc.z * ii, acc.w * ii);
                *(float4*)&aggf[li * 132 + lane * 4] = o;
            }
        } else {
            for (int li = wp; li < NPG; li += 16) {
                int lo = off_s[li], hi = off_s[li + 1];
                float4 acc = make_float4(0.f, 0.f, 0.f, 0.f);
                for (int e = lo; e < hi; e++) {
                    int sl = d_esrc[e];
                    float4 v = ((const float4*)h1m)[sl * 32 + lane];
                    acc.x += v.x; acc.y += v.y; acc.z += v.z; acc.w += v.w;
                }
                float ii = invin[li];
                float4 o = make_float4(acc.x * ii, acc.y * ii, acc.z * ii, acc.w * ii);
                *(float4*)&aggf[li * 132 + lane * 4] = o;
            }
        }
        __syncthreads();

        // phase c: 3xTF32 MMA — 14 warps: (mtile 0..6) x (nhalf 0..1)
        if (wp < 14) {
            int mt = wp >> 1, nh = wp & 1;
            int row = mt * 16 + (lane >> 2);
            int kk = lane & 3;
            float acc[8][4];
#pragma unroll
            for (int nt = 0; nt < 8; nt++)
#pragma unroll
                for (int q = 0; q < 4; q++) acc[nt][q] = 0.f;
#pragma unroll
            for (int k0 = 0; k0 < HID; k0 += 8) {
                float af0 = aggf[row * 132 + k0 + kk];
                float af1 = aggf[(row + 8) * 132 + k0 + kk];
                float af2 = aggf[row * 132 + k0 + kk + 4];
                float af3 = aggf[(row + 8) * 132 + k0 + kk + 4];
                unsigned ah0, al0, ah1, al1, ah2, al2, ah3, al3;
                tf32split(af0, ah0, al0);
                tf32split(af1, ah1, al1);
                tf32split(af2, ah2, al2);
                tf32split(af3, ah3, al3);
#pragma unroll
                for (int nt = 0; nt < 8; nt++) {
                    int ncol = nh * 64 + nt * 8 + (lane >> 2);
                    float bf0 = W2s[(k0 + kk) * 136 + ncol];
                    float bf1 = W2s[(k0 + kk + 4) * 136 + ncol];
                    unsigned bh0, bl0, bh1, bl1;
                    tf32split(bf0, bh0, bl0);
                    tf32split(bf1, bh1, bl1);
                    asm volatile(
                        "mma.sync.aligned.m16n8k8.row.col.f32.tf32.tf32.f32 "
                        "{%0,%1,%2,%3}, {%4,%5,%6,%7}, {%8,%9}, {%0,%1,%2,%3};"
                        : "+f"(acc[nt][0]), "+f"(acc[nt][1]),
                          "+f"(acc[nt][2]), "+f"(acc[nt][3])
                        : "r"(ah0), "r"(ah1), "r"(ah2), "r"(ah3), "r"(bh0), "r"(bh1));
                    asm volatile(
                        "mma.sync.aligned.m16n8k8.row.col.f32.tf32.tf32.f32 "
                        "{%0,%1,%2,%3}, {%4,%5,%6,%7}, {%8,%9}, {%0,%1,%2,%3};"
                        : "+f"(acc[nt][0]), "+f"(acc[nt][1]),
                          "+f"(acc[nt][2]), "+f"(acc[nt][3])
                        : "r"(al0), "r"(al1), "r"(al2), "r"(al3), "r"(bh0), "r"(bh1));
                    asm volatile(
                        "mma.sync.aligned.m16n8k8.row.col.f32.tf32.tf32.f32 "
                        "{%0,%1,%2,%3}, {%4,%5,%6,%7}, {%8,%9}, {%0,%1,%2,%3};"
                        : "+f"(acc[nt][0]), "+f"(acc[nt][1]),
                          "+f"(acc[nt][2]), "+f"(acc[nt][3])
                        : "r"(ah0), "r"(ah1), "r"(ah2), "r"(ah3), "r"(bl0), "r"(bl1));
                }
            }
            long gi0 = ((long)g * NPG + row) * HID;
            long gi1 = ((long)g * NPG + row + 8) * HID;
#pragma unroll
            for (int nt = 0; nt < 8; nt++) {
                int c0 = nh * 64 + nt * 8 + 2 * (lane & 3);
                float bx = b2s[c0], by = b2s[c0 + 1];
                if (row < NPG)
                    *(float2*)&d_pre[gi0 + c0] = make_float2(acc[nt][0] + bx, acc[nt][1] + by);
                if (row + 8 < NPG)
                    *(float2*)&d_pre[gi1 + c0] = make_float2(acc[nt][2] + bx, acc[nt][3] + by);
            }
        }
        __syncthreads();
    }
}

__global__ void k_bn2stats() {
    int c = threadIdx.x;
    float s = 0.f, q = 0.f;
    for (int r = blockIdx.x; r < N_NODES; r += gridDim.x) {
        float v = d_pre[r * HID + c];
        s += v; q += v * v;
    }
    atomicAdd(&d_bn2s[c], s);
    atomicAdd(&d_bn2q[c], q);
}

// per-graph tail: bn2+elu -> h2(smem); t = inv_out*(h2.Wv); d from CSR; vec readout
#define GT_T 128
__global__ __launch_bounds__(GT_T)
void k_gtail(const float* __restrict__ g2, const float* __restrict__ be2,
             const float* __restrict__ Wv, const float* __restrict__ bv) {
    __shared__ float h2s[NPG * HID];   // 51200 B
    __shared__ float al2[HID];
    __shared__ float bt2[HID];
    __shared__ float ts[NPG];
    __shared__ float ds[NPG];
    __shared__ float ws[4];
    int g = blockIdx.x, tid = threadIdx.x;
    int wp = tid >> 5, lane = tid & 31;

    if (tid < HID) {
        float invN = 1.f / (float)N_NODES;
        float mu = d_bn2s[tid] * invN;
        float var = d_bn2q[tid] * invN - mu * mu;
        float a = g2[tid] * rsqrtf(var + EPS);
        al2[tid] = a;
        bt2[tid] = be2[tid] - mu * a;
    }
    __syncthreads();

    // phase 1: load pre2 slice, bn + elu -> h2s
    const float4* P = (const float4*)(d_pre + (long)g * NPG * HID);
    for (int idx = tid; idx < NPG * 32; idx += GT_T) {
        float4 v = P[idx];
        int c4 = (idx & 31) * 4;
        float4 a4 = *(const float4*)&al2[c4];
        float4 b4 = *(const float4*)&bt2[c4];
        v.x = fast_elu(v.x * a4.x + b4.x);
        v.y = fast_elu(v.y * a4.y + b4.y);
        v.z = fast_elu(v.z * a4.z + b4.z);
        v.w = fast_elu(v.w * a4.w + b4.w);
        ((float4*)h2s)[idx] = v;
    }
    __syncthreads();

    // phase 2: t[j] = inv_out * dot(h2[j], Wv)  (warp per node)
    float4 w4 = ((const float4*)Wv)[lane];
    for (int j = wp; j < NPG; j += 4) {
        float4 h = ((const float4*)h2s)[j * 32 + lane];
        float s = h.x * w4.x + h.y * w4.y + h.z * w4.z + h.w * w4.w;
        for (int o = 16; o > 0; o >>= 1) s += __shfl_xor_sync(0xffffffffu, s, o);
        if (lane == 0) ts[j] = s * d_inv_out[g * NPG + j];
    }
    __syncthreads();

    // phase 3: d[i] = inv_in*sum(t[src]) + bv
    float bv0 = bv[0];
    if (tid < NPG) {
        int i = g * NPG + tid;
        int lo = d_off[i], hi = d_off[i + 1];
        float a = 0.f;
        for (int e = lo; e < hi; e++) a += ts[d_esrc[e]];
        ds[tid] = d_inv_in[i] * a + bv0;
    }
    __syncthreads();

    // phase 4: vec[g][c] = sum_j d[j] * h2[j][c]
    float acc = 0.f;
    for (int j = 0; j < NPG; j++)
        acc += ds[j] * h2s[j * HID + tid];
    d_vec[g * HID + tid] = acc;
    float s = acc;
    for (int o = 16; o > 0; o >>= 1) s += __shfl_xor_sync(0xffffffffu, s, o);
    if (lane == 0) ws[wp] = s;
    __syncthreads();
    if (tid == 0) atomicAdd(&d_meanAcc, ws[0] + ws[1] + ws[2] + ws[3]);
}

// shrink+tanh fused into FC: z = tanh(shrink(vec)) @ Wg + bg ; bn3 stats
#define FCR 8
__global__ void k_fc(const float* __restrict__ Wg, const float* __restrict__ bg) {
    __shared__ float rowS[FCR][HID];
    int c = threadIdx.x;
    int r0 = blockIdx.x * FCR;
    float mean = d_meanAcc * (1.f / (BATCH * HID));
    for (int nd = 0; nd < FCR; nd++) {
        float x = d_vec[(r0 + nd) * HID + c];
        float sv = fmaxf(x - mean, 0.f) - fmaxf(-x - mean, 0.f);
        rowS[nd][c] = tanhf(sv);
    }
    __syncthreads();
    float acc[FCR];
    float bgc = bg[c];
#pragma unroll
    for (int nd = 0; nd < FCR; nd++) acc[nd] = bgc;
    for (int k = 0; k < HID; k += 4) {
        float w0 = Wg[(k + 0) * HID + c];
        float w1 = Wg[(k + 1) * HID + c];
        float w2 = Wg[(k + 2) * HID + c];
        float w3 = Wg[(k + 3) * HID + c];
#pragma unroll
        for (int nd = 0; nd < FCR; nd++) {
            float4 a = *reinterpret_cast<float4*>(&rowS[nd][k]);
            acc[nd] += a.x * w0 + a.y * w1 + a.z * w2 + a.w * w3;
        }
    }
    float s1 = 0.f, s2 = 0.f;
#pragma unroll
    for (int nd = 0; nd < FCR; nd++) {
        float y = acc[nd];
        d_z[(r0 + nd) * HID + c] = y;
        s1 += y; s2 += y * y;
    }
    atomicAdd(&d_bn3s[c], s1);
    atomicAdd(&d_bn3q[c], s2);
}

__global__ void k_final(const float* __restrict__ g3, const float* __restrict__ be3,
                        const float* __restrict__ Wc, const float* __restrict__ bc,
                        float* __restrict__ out) {
    __shared__ float hs[HID];
    int b = blockIdx.x, c = threadIdx.x;
    float inv = 1.f / (float)BATCH;
    float mu = d_bn3s[c] * inv;
    float var = d_bn3q[c] * inv - mu * mu;
    float rstd = rsqrtf(var + EPS);
    float v = tanhf((d_z[b * HID + c] - mu) * rstd * g3[c] + be3[c]);
    hs[c] = v;
    __syncthreads();
    if (c < NC) {
        float a = bc[c];
        for (int k = 0; k < HID; k++)
            a += hs[k] * Wc[k * NC + c];
        out[b * NC + c] = tanhf(a);
    }
}

// ---------------- launch ----------------
extern "C" void kernel_launch(void* const* d_in, const int* in_sizes, int n_in,
                              void* d_out, int out_size) {
    const int*   src = (const int*)d_in[0];
    const int*   dst = (const int*)d_in[1];
    const float* W1  = (const float*)d_in[3];
    const float* b1  = (const float*)d_in[4];
    const float* g1  = (const float*)d_in[5];
    const float* be1 = (const float*)d_in[6];
    const float* W2  = (const float*)d_in[7];
    const float* b2  = (const float*)d_in[8];
    const float* g2  = (const float*)d_in[9];
    const float* be2 = (const float*)d_in[10];
    const float* Wv  = (const float*)d_in[11];
    const float* bv  = (const float*)d_in[12];
    const float* Wg  = (const float*)d_in[15];
    const float* bg  = (const float*)d_in[16];
    const float* g3  = (const float*)d_in[17];
    const float* be3 = (const float*)d_in[18];
    const float* Wc  = (const float*)d_in[19];
    const float* bc  = (const float*)d_in[20];
    float* out = (float*)d_out;

    static int smem_set = 0;
    const int L2_SMEM = (128 * 136 + 112 * 132 + 100 * 128 + 20 * 128 + 100 * IND
                         + 3 * 128 + 2 * 100) * 4 + 104 * 4 + ECAP * 4;
    if (!smem_set) {
        cudaFuncSetAttribute(k_layer2, cudaFuncAttributeMaxDynamicSharedMemorySize, L2_SMEM);
        smem_set = 1;
    }

    k_zero<<<(N_NODES * IND + 255) / 256, 256>>>();
    k_deg<<<(N_EDGES + 255) / 256, 256>>>(src, dst);
    k_nodescan<<<80, 1024>>>();
    k_bucketscat<<<(N_EDGES + 255) / 256, 256>>>(src, dst);
    k_sort<<<BATCH, 128>>>();
    k_l1stats<<<N_NODES / L1N, HID>>>(W1, b1);
    k_layer2<<<148, L2T, L2_SMEM>>>(g1, be1, W1, b1, W2, b2);
    k_bn2stats<<<400, HID>>>();
    k_gtail<<<BATCH, GT_T>>>(g2, be2, Wv, bv);
    k_fc<<<BATCH / FCR, HID>>>(Wg, bg);
    k_final<<<BATCH, HID>>>(g3, be3, Wc, bc, out);
}

// round 12
// speedup vs baseline: 1.6419x; 1.3374x over previous
#include <cuda_runtime.h>
#include <cuda_bf16.h>
#include <math.h>

#define N_NODES 80000
#define N_EDGES 640000
#define BATCH   800
#define NPG     100
#define HID     128
#define NC      10
#define IND     20
#define EPS     1e-5f
#define ECAP    1280

// ---------------- scratch ----------------
__device__ int    d_deg_in[N_NODES];
__device__ int    d_deg_out[N_NODES];
__device__ float  d_inv_in[N_NODES];
__device__ float  d_inv_out[N_NODES];
__device__ float2 d_ninfo[N_NODES];           // (inv_out, cls)

__device__ int   d_goff[BATCH + 1];
__device__ int   d_off[N_NODES + 1];
__device__ int   d_cur[N_NODES];
__device__ int   d_esrc[N_EDGES];             // LOCAL src id, CSR by dst

__device__ float d_acc20[N_NODES * IND];

__device__ float d_pre[N_NODES * HID];        // pre2 only
__device__ float d_vec[BATCH * HID];
__device__ float d_z[BATCH * HID];

__device__ float d_bn1s[HID], d_bn1q[HID];
__device__ float d_bn2s[HID], d_bn2q[HID];
__device__ float d_bn3s[HID], d_bn3q[HID];
__device__ float d_meanAcc;

__device__ __forceinline__ unsigned f2tf32(float x) {
    unsigned r; asm("cvt.rna.tf32.f32 %0, %1;" : "=r"(r) : "f"(x)); return r;
}
__device__ __forceinline__ void tf32split(float x, unsigned& hi, unsigned& lo) {
    hi = f2tf32(x);
    lo = f2tf32(x - __uint_as_float(hi));
}
__device__ __forceinline__ float fast_elu(float y) {
    return y > 0.f ? y : (__expf(y) - 1.0f);
}

// ---------------- kernels ----------------

__global__ void k_zero() {
    int i = blockIdx.x * blockDim.x + threadIdx.x;   // grid covers 1.6M
    if (i < N_NODES * IND) d_acc20[i] = 0.f;
    if (i < N_NODES) { d_deg_in[i] = 0; d_deg_out[i] = 0; }
    if (i < HID) {
        d_bn1s[i] = 0.f; d_bn1q[i] = 0.f;
        d_bn2s[i] = 0.f; d_bn2q[i] = 0.f;
        d_bn3s[i] = 0.f; d_bn3q[i] = 0.f;
    }
    if (i == 0) d_meanAcc = 0.f;
}

// degree counting: spread atomics only (80k addresses)
__global__ void k_deg(const int* __restrict__ src, const int* __restrict__ dst) {
    int e = blockIdx.x * blockDim.x + threadIdx.x;
    if (e >= N_EDGES) return;
    atomicAdd(&d_deg_out[src[e]], 1);
    atomicAdd(&d_deg_in[dst[e]], 1);
}

__global__ void k_node() {
    int i = blockIdx.x * blockDim.x + threadIdx.x;
    if (i >= N_NODES) return;
    int di = d_deg_in[i], dout = d_deg_out[i];
    float ii = rsqrtf((float)(di   > 1 ? di   : 1));
    float io = rsqrtf((float)(dout > 1 ? dout : 1));
    d_inv_in[i] = ii;
    d_inv_out[i] = io;
    int cls = di < (IND - 1) ? di : (IND - 1);
    d_ninfo[i] = make_float2(io, (float)cls);
}

// per-graph edge counts from deg_in (no edge pass) + scan -> d_goff
__global__ void k_gscan() {
    __shared__ int s[1024];
    int t = threadIdx.x;
    int sum = 0;
    if (t < BATCH) {
        const int* p = d_deg_in + t * NPG;
#pragma unroll 4
        for (int j = 0; j < NPG; j++) sum += p[j];
    }
    s[t] = sum;
    __syncthreads();
    for (int o = 1; o < 1024; o <<= 1) {
        int v = (t >= o) ? s[t - o] : 0;
        __syncthreads();
        s[t] += v;
        __syncthreads();
    }
    if (t < BATCH) d_goff[t + 1] = s[t];
    if (t == 0) d_goff[0] = 0;
}

// per-graph node offsets (scan of 100 in-degrees) -> d_off, d_cur
__global__ void k_offsets() {
    __shared__ int s[NPG];
    int g = blockIdx.x, t = threadIdx.x;
    int deg = 0;
    if (t < NPG) { deg = d_deg_in[g * NPG + t]; s[t] = deg; }
    __syncthreads();
    for (int o = 1; o < NPG; o <<= 1) {
        int v = 0;
        if (t < NPG && t >= o) v = s[t - o];
        __syncthreads();
        if (t < NPG && t >= o) s[t] += v;
        __syncthreads();
    }
    if (t < NPG) {
        int off = d_goff[g] + s[t] - deg;
        d_off[g * NPG + t] = off;
        d_cur[g * NPG + t] = off;
    }
    if (g == 0 && t == 0) d_off[N_NODES] = N_EDGES;
}

// single edge pass: CSR scatter (80k cursors) + 20-class scatter
__global__ void k_scatter(const int* __restrict__ src, const int* __restrict__ dst) {
    int e = blockIdx.x * blockDim.x + threadIdx.x;
    if (e >= N_EDGES) return;
    int s = src[e], d = dst[e];
    int pos = atomicAdd(&d_cur[d], 1);
    d_esrc[pos] = s % NPG;               // src local id (same graph as dst)
    float2 ni = d_ninfo[s];
    atomicAdd(&d_acc20[d * IND + (int)ni.y], ni.x);
}

// bn1 stats only (pre1 never stored)
#define L1N 64
__global__ void k_l1stats(const float* __restrict__ W1, const float* __restrict__ b1) {
    __shared__ float a20[L1N * IND];
    __shared__ float invs[L1N];
    int c = threadIdx.x;
    int base = blockIdx.x * L1N;
    for (int idx = c; idx < L1N * IND; idx += HID)
        a20[idx] = d_acc20[base * IND + idx];
    if (c < L1N) invs[c] = d_inv_in[base + c];
    float w1r[IND];
#pragma unroll
    for (int k = 0; k < IND; k++) w1r[k] = W1[k * HID + c];
    float b1c = b1[c];
    __syncthreads();
    float s1 = 0.f, s2 = 0.f;
    for (int nd = 0; nd < L1N; nd++) {
        float acc = 0.f;
#pragma unroll
        for (int k = 0; k < IND; k++) acc += a20[nd * IND + k] * w1r[k];
        float y = acc * invs[nd] + b1c;
        s1 += y; s2 += y * y;
    }
    atomicAdd(&d_bn1s[c], s1);
    atomicAdd(&d_bn1q[c], s2);
}

// ---------- layer 2: persistent; recompute pre1 from acc20, agg, 3xTF32 MMA ----------
#define L2T 512
__global__ __launch_bounds__(L2T, 1)
void k_layer2(const float* __restrict__ g1, const float* __restrict__ be1,
              const float* __restrict__ W1, const float* __restrict__ b1,
              const float* __restrict__ W2, const float* __restrict__ b2) {
    extern __shared__ float smem[];
    float*    W2s    = smem;                       // 128*136
    float*    aggf   = W2s + 128 * 136;            // 112*132
    float*    h1m    = aggf + 112 * 132;           // 100*128
    float*    W1s    = h1m + 100 * 128;            // 20*128
    float*    a20s   = W1s + 20 * 128;             // 100*20
    float*    alpha  = a20s + 100 * IND;           // 128 (bn1 scale)
    float*    beta1p = alpha + 128;                // 128 (alpha*b1 + beta)
    float*    b2s    = beta1p + 128;               // 128
    float*    invin  = b2s + 128;                  // 100
    float*    invout = invin + 100;                // 100
    int*      off_s  = (int*)(invout + 100);       // 104
    int*      esrc_s = off_s + 104;                // ECAP

    int tid = threadIdx.x;
    int wp = tid >> 5, lane = tid & 31;

    // one-time init
    for (int idx = tid; idx < HID * HID; idx += L2T) {
        int k = idx >> 7, n = idx & 127;
        W2s[k * 136 + n] = W2[idx];
    }
    for (int idx = tid; idx < IND * HID; idx += L2T)
        W1s[idx] = W1[idx];
    if (tid < HID) {
        float invN = 1.f / (float)N_NODES;
        float mu = d_bn1s[tid] * invN;
        float var = d_bn1q[tid] * invN - mu * mu;
        float rstd = rsqrtf(var + EPS);
        float a = g1[tid] * rstd;
        alpha[tid] = a;
        beta1p[tid] = a * b1[tid] + (be1[tid] - mu * a);
        b2s[tid] = b2[tid];
    }
    for (int idx = tid; idx < 12 * 132; idx += L2T)
        aggf[100 * 132 + idx] = 0.f;               // zero pad rows 100..111
    __syncthreads();

    // per-thread persistent W1 column + bn consts
    int cc = tid & 127;
    int grp = tid >> 7;                            // 0..3 -> li block of 25
    float w1c[IND];
#pragma unroll
    for (int k = 0; k < IND; k++) w1c[k] = W1s[k * HID + cc];
    float alpha_c = alpha[cc], beta_c = beta1p[cc];

    for (int g = blockIdx.x; g < BATCH; g += gridDim.x) {
        // phase 0: stage per-graph data
        for (int idx = tid; idx < NPG * IND; idx += L2T)
            a20s[idx] = d_acc20[g * NPG * IND + idx];
        if (tid < NPG) {
            invin[tid]  = d_inv_in[g * NPG + tid];
            invout[tid] = d_inv_out[g * NPG + tid];
        }
        if (tid >= 128 && tid - 128 <= NPG) off_s[tid - 128] = d_off[g * NPG + tid - 128];
        int eB = d_off[g * NPG];
        int eE = d_off[g * NPG + NPG];
        int cnt = eE - eB;
        for (int idx = tid; idx < cnt && idx < ECAP; idx += L2T)
            esrc_s[idx] = d_esrc[eB + idx];
        __syncthreads();

        // phase a: recompute pre1 -> bn1 -> elu -> *inv_out -> h1m
        for (int li = grp * 25; li < grp * 25 + 25; li++) {
            float acc = 0.f;
#pragma unroll
            for (int k = 0; k < IND; k++) acc += a20s[li * IND + k] * w1c[k];
            float h = fast_elu(acc * (alpha_c * invin[li]) + beta_c) * invout[li];
            h1m[li * HID + cc] = h;
        }
        __syncthreads();

        // phase b: aggregation (warp per node, float4 channels)
        if (cnt <= ECAP) {
            for (int li = wp; li < NPG; li += 16) {
                int lo = off_s[li], hi = off_s[li + 1];
                float4 acc = make_float4(0.f, 0.f, 0.f, 0.f);
                for (int e = lo; e < hi; e++) {
                    int sl = esrc_s[e - eB];
                    float4 v = ((const float4*)h1m)[sl * 32 + lane];
                    acc.x += v.x; acc.y += v.y; acc.z += v.z; acc.w += v.w;
                }
                float ii = invin[li];
                float4 o = make_float4(acc.x * ii, acc.y * ii, acc.z * ii, acc.w * ii);
                *(float4*)&aggf[li * 132 + lane * 4] = o;
            }
        } else {
            for (int li = wp; li < NPG; li += 16) {
                int lo = off_s[li], hi = off_s[li + 1];
                float4 acc = make_float4(0.f, 0.f, 0.f, 0.f);
                for (int e = lo; e < hi; e++) {
                    int sl = d_esrc[e];
                    float4 v = ((const float4*)h1m)[sl * 32 + lane];
                    acc.x += v.x; acc.y += v.y; acc.z += v.z; acc.w += v.w;
                }
                float ii = invin[li];
                float4 o = make_float4(acc.x * ii, acc.y * ii, acc.z * ii, acc.w * ii);
                *(float4*)&aggf[li * 132 + lane * 4] = o;
            }
        }
        __syncthreads();

        // phase c: 3xTF32 MMA — 14 warps: (mtile 0..6) x (nhalf 0..1)
        if (wp < 14) {
            int mt = wp >> 1, nh = wp & 1;
            int row = mt * 16 + (lane >> 2);
            int kk = lane & 3;
            float acc[8][4];
#pragma unroll
            for (int nt = 0; nt < 8; nt++)
#pragma unroll
                for (int q = 0; q < 4; q++) acc[nt][q] = 0.f;
#pragma unroll
            for (int k0 = 0; k0 < HID; k0 += 8) {
                float af0 = aggf[row * 132 + k0 + kk];
                float af1 = aggf[(row + 8) * 132 + k0 + kk];
                float af2 = aggf[row * 132 + k0 + kk + 4];
                float af3 = aggf[(row + 8) * 132 + k0 + kk + 4];
                unsigned ah0, al0, ah1, al1, ah2, al2, ah3, al3;
                tf32split(af0, ah0, al0);
                tf32split(af1, ah1, al1);
                tf32split(af2, ah2, al2);
                tf32split(af3, ah3, al3);
#pragma unroll
                for (int nt = 0; nt < 8; nt++) {
                    int ncol = nh * 64 + nt * 8 + (lane >> 2);
                    float bf0 = W2s[(k0 + kk) * 136 + ncol];
                    float bf1 = W2s[(k0 + kk + 4) * 136 + ncol];
                    unsigned bh0, bl0, bh1, bl1;
                    tf32split(bf0, bh0, bl0);
                    tf32split(bf1, bh1, bl1);
                    asm volatile(
                        "mma.sync.aligned.m16n8k8.row.col.f32.tf32.tf32.f32 "
                        "{%0,%1,%2,%3}, {%4,%5,%6,%7}, {%8,%9}, {%0,%1,%2,%3};"
                        : "+f"(acc[nt][0]), "+f"(acc[nt][1]),
                          "+f"(acc[nt][2]), "+f"(acc[nt][3])
                        : "r"(ah0), "r"(ah1), "r"(ah2), "r"(ah3), "r"(bh0), "r"(bh1));
                    asm volatile(
                        "mma.sync.aligned.m16n8k8.row.col.f32.tf32.tf32.f32 "
                        "{%0,%1,%2,%3}, {%4,%5,%6,%7}, {%8,%9}, {%0,%1,%2,%3};"
                        : "+f"(acc[nt][0]), "+f"(acc[nt][1]),
                          "+f"(acc[nt][2]), "+f"(acc[nt][3])
                        : "r"(al0), "r"(al1), "r"(al2), "r"(al3), "r"(bh0), "r"(bh1));
                    asm volatile(
                        "mma.sync.aligned.m16n8k8.row.col.f32.tf32.tf32.f32 "
                        "{%0,%1,%2,%3}, {%4,%5,%6,%7}, {%8,%9}, {%0,%1,%2,%3};"
                        : "+f"(acc[nt][0]), "+f"(acc[nt][1]),
                          "+f"(acc[nt][2]), "+f"(acc[nt][3])
                        : "r"(ah0), "r"(ah1), "r"(ah2), "r"(ah3), "r"(bl0), "r"(bl1));
                }
            }
            long gi0 = ((long)g * NPG + row) * HID;
            long gi1 = ((long)g * NPG + row + 8) * HID;
#pragma unroll
            for (int nt = 0; nt < 8; nt++) {
                int c0 = nh * 64 + nt * 8 + 2 * (lane & 3);
                float bx = b2s[c0], by = b2s[c0 + 1];
                if (row < NPG)
                    *(float2*)&d_pre[gi0 + c0] = make_float2(acc[nt][0] + bx, acc[nt][1] + by);
                if (row + 8 < NPG)
                    *(float2*)&d_pre[gi1 + c0] = make_float2(acc[nt][2] + bx, acc[nt][3] + by);
            }
        }
        __syncthreads();
    }
}

__global__ void k_bn2stats() {
    int c = threadIdx.x;
    float s = 0.f, q = 0.f;
    for (int r = blockIdx.x; r < N_NODES; r += gridDim.x) {
        float v = d_pre[r * HID + c];
        s += v; q += v * v;
    }
    atomicAdd(&d_bn2s[c], s);
    atomicAdd(&d_bn2q[c], q);
}

// per-graph tail: bn2+elu -> h2(smem); t = inv_out*(h2.Wv); d from CSR; vec readout
#define GT_T 128
__global__ __launch_bounds__(GT_T)
void k_gtail(const float* __restrict__ g2, const float* __restrict__ be2,
             const float* __restrict__ Wv, const float* __restrict__ bv) {
    __shared__ float h2s[NPG * HID];   // 51200 B
    __shared__ float al2[HID];
    __shared__ float bt2[HID];
    __shared__ float ts[NPG];
    __shared__ float ds[NPG];
    __shared__ float ws[4];
    int g = blockIdx.x, tid = threadIdx.x;
    int wp = tid >> 5, lane = tid & 31;

    if (tid < HID) {
        float invN = 1.f / (float)N_NODES;
        float mu = d_bn2s[tid] * invN;
        float var = d_bn2q[tid] * invN - mu * mu;
        float a = g2[tid] * rsqrtf(var + EPS);
        al2[tid] = a;
        bt2[tid] = be2[tid] - mu * a;
    }
    __syncthreads();

    // phase 1: load pre2 slice, bn + elu -> h2s
    const float4* P = (const float4*)(d_pre + (long)g * NPG * HID);
    for (int idx = tid; idx < NPG * 32; idx += GT_T) {
        float4 v = P[idx];
        int c4 = (idx & 31) * 4;
        float4 a4 = *(const float4*)&al2[c4];
        float4 b4 = *(const float4*)&bt2[c4];
        v.x = fast_elu(v.x * a4.x + b4.x);
        v.y = fast_elu(v.y * a4.y + b4.y);
        v.z = fast_elu(v.z * a4.z + b4.z);
        v.w = fast_elu(v.w * a4.w + b4.w);
        ((float4*)h2s)[idx] = v;
    }
    __syncthreads();

    // phase 2: t[j] = inv_out * dot(h2[j], Wv)  (warp per node)
    float4 w4 = ((const float4*)Wv)[lane];
    for (int j = wp; j < NPG; j += 4) {
        float4 h = ((const float4*)h2s)[j * 32 + lane];
        float s = h.x * w4.x + h.y * w4.y + h.z * w4.z + h.w * w4.w;
        for (int o = 16; o > 0; o >>= 1) s += __shfl_xor_sync(0xffffffffu, s, o);
        if (lane == 0) ts[j] = s * d_inv_out[g * NPG + j];
    }
    __syncthreads();

    // phase 3: d[i] = inv_in*sum(t[src]) + bv
    float bv0 = bv[0];
    if (tid < NPG) {
        int i = g * NPG + tid;
        int lo = d_off[i], hi = d_off[i + 1];
        float a = 0.f;
        for (int e = lo; e < hi; e++) a += ts[d_esrc[e]];
        ds[tid] = d_inv_in[i] * a + bv0;
    }
    __syncthreads();

    // phase 4: vec[g][c] = sum_j d[j] * h2[j][c]
    float acc = 0.f;
    for (int j = 0; j < NPG; j++)
        acc += ds[j] * h2s[j * HID + tid];
    d_vec[g * HID + tid] = acc;
    float s = acc;
    for (int o = 16; o > 0; o >>= 1) s += __shfl_xor_sync(0xffffffffu, s, o);
    if (lane == 0) ws[wp] = s;
    __syncthreads();
    if (tid == 0) atomicAdd(&d_meanAcc, ws[0] + ws[1] + ws[2] + ws[3]);
}

// shrink+tanh fused into FC: z = tanh(shrink(vec)) @ Wg + bg ; bn3 stats
#define FCR 8
__global__ void k_fc(const float* __restrict__ Wg, const float* __restrict__ bg) {
    __shared__ float rowS[FCR][HID];
    int c = threadIdx.x;
    int r0 = blockIdx.x * FCR;
    float mean = d_meanAcc * (1.f / (BATCH * HID));
    for (int nd = 0; nd < FCR; nd++) {
        float x = d_vec[(r0 + nd) * HID + c];
        float sv = fmaxf(x - mean, 0.f) - fmaxf(-x - mean, 0.f);
        rowS[nd][c] = tanhf(sv);
    }
    __syncthreads();
    float acc[FCR];
    float bgc = bg[c];
#pragma unroll
    for (int nd = 0; nd < FCR; nd++) acc[nd] = bgc;
    for (int k = 0; k < HID; k += 4) {
        float w0 = Wg[(k + 0) * HID + c];
        float w1 = Wg[(k + 1) * HID + c];
        float w2 = Wg[(k + 2) * HID + c];
        float w3 = Wg[(k + 3) * HID + c];
#pragma unroll
        for (int nd = 0; nd < FCR; nd++) {
            float4 a = *reinterpret_cast<float4*>(&rowS[nd][k]);
            acc[nd] += a.x * w0 + a.y * w1 + a.z * w2 + a.w * w3;
        }
    }
    float s1 = 0.f, s2 = 0.f;
#pragma unroll
    for (int nd = 0; nd < FCR; nd++) {
        float y = acc[nd];
        d_z[(r0 + nd) * HID + c] = y;
        s1 += y; s2 += y * y;
    }
    atomicAdd(&d_bn3s[c], s1);
    atomicAdd(&d_bn3q[c], s2);
}

__global__ void k_final(const float* __restrict__ g3, const float* __restrict__ be3,
                        const float* __restrict__ Wc, const float* __restrict__ bc,
                        float* __restrict__ out) {
    __shared__ float hs[HID];
    int b = blockIdx.x, c = threadIdx.x;
    float inv = 1.f / (float)BATCH;
    float mu = d_bn3s[c] * inv;
    float var = d_bn3q[c] * inv - mu * mu;
    float rstd = rsqrtf(var + EPS);
    float v = tanhf((d_z[b * HID + c] - mu) * rstd * g3[c] + be3[c]);
    hs[c] = v;
    __syncthreads();
    if (c < NC) {
        float a = bc[c];
        for (int k = 0; k < HID; k++)
            a += hs[k] * Wc[k * NC + c];
        out[b * NC + c] = tanhf(a);
    }
}

// ---------------- launch ----------------
extern "C" void kernel_launch(void* const* d_in, const int* in_sizes, int n_in,
                              void* d_out, int out_size) {
    const int*   src = (const int*)d_in[0];
    const int*   dst = (const int*)d_in[1];
    const float* W1  = (const float*)d_in[3];
    const float* b1  = (const float*)d_in[4];
    const float* g1  = (const float*)d_in[5];
    const float* be1 = (const float*)d_in[6];
    const float* W2  = (const float*)d_in[7];
    const float* b2  = (const float*)d_in[8];
    const float* g2  = (const float*)d_in[9];
    const float* be2 = (const float*)d_in[10];
    const float* Wv  = (const float*)d_in[11];
    const float* bv  = (const float*)d_in[12];
    const float* Wg  = (const float*)d_in[15];
    const float* bg  = (const float*)d_in[16];
    const float* g3  = (const float*)d_in[17];
    const float* be3 = (const float*)d_in[18];
    const float* Wc  = (const float*)d_in[19];
    const float* bc  = (const float*)d_in[20];
    float* out = (float*)d_out;

    static int smem_set = 0;
    const int L2_SMEM = (128 * 136 + 112 * 132 + 100 * 128 + 20 * 128 + 100 * IND
                         + 3 * 128 + 2 * 100) * 4 + 104 * 4 + ECAP * 4;
    if (!smem_set) {
        cudaFuncSetAttribute(k_layer2, cudaFuncAttributeMaxDynamicSharedMemorySize, L2_SMEM);
        smem_set = 1;
    }

    k_zero<<<(N_NODES * IND + 255) / 256, 256>>>();
    k_deg<<<(N_EDGES + 255) / 256, 256>>>(src, dst);
    k_node<<<(N_NODES + 1023) / 1024, 1024>>>();
    k_gscan<<<1, 1024>>>();
    k_offsets<<<BATCH, 128>>>();
    k_scatter<<<(N_EDGES + 255) / 256, 256>>>(src, dst);
    k_l1stats<<<N_NODES / L1N, HID>>>(W1, b1);
    k_layer2<<<148, L2T, L2_SMEM>>>(g1, be1, W1, b1, W2, b2);
    k_bn2stats<<<400, HID>>>();
    k_gtail<<<BATCH, GT_T>>>(g2, be2, Wv, bv);
    k_fc<<<BATCH / FCR, HID>>>(Wg, bg);
    k_final<<<BATCH, HID>>>(g3, be3, Wc, bc, out);
}

// round 14
// speedup vs baseline: 1.7317x; 1.0547x over previous
#include <cuda_runtime.h>
#include <cuda_bf16.h>
#include <math.h>

#define N_NODES 80000
#define N_EDGES 640000
#define BATCH   800
#define NPG     100
#define HID     128
#define NC      10
#define IND     20
#define EPS     1e-5f
#define ECAP    1280

// ---------------- scratch ----------------
__device__ int    d_deg_in[N_NODES];
__device__ int    d_deg_out[N_NODES];
__device__ float  d_inv_in[N_NODES];
__device__ float  d_inv_out[N_NODES];
__device__ float2 d_ninfo[N_NODES];           // (inv_out, cls)

__device__ int   d_gsum[BATCH];
__device__ int   d_goff[BATCH + 1];
__device__ int   d_off[N_NODES + 1];
__device__ int   d_cur[N_NODES];
__device__ int   d_esrc[N_EDGES];             // LOCAL src id, CSR by dst

__device__ float d_acc20[N_NODES * IND];

__device__ float d_pre[N_NODES * HID];        // pre2 only
__device__ float d_vec[BATCH * HID];
__device__ float d_z[BATCH * HID];

__device__ float d_bn1s[HID], d_bn1q[HID];
__device__ float d_bn2s[HID], d_bn2q[HID];
__device__ float d_bn3s[HID], d_bn3q[HID];
__device__ float d_meanAcc;

__device__ __forceinline__ unsigned f2tf32(float x) {
    unsigned r; asm("cvt.rna.tf32.f32 %0, %1;" : "=r"(r) : "f"(x)); return r;
}
__device__ __forceinline__ void tf32split(float x, unsigned& hi, unsigned& lo) {
    hi = f2tf32(x);
    lo = f2tf32(x - __uint_as_float(hi));
}
__device__ __forceinline__ float fast_elu(float y) {
    return y > 0.f ? y : (__expf(y) - 1.0f);
}

// ---------------- kernels ----------------

__global__ void k_zero() {
    int i = blockIdx.x * blockDim.x + threadIdx.x;   // grid covers 1.6M
    if (i < N_NODES * IND) d_acc20[i] = 0.f;
    if (i < N_NODES) { d_deg_in[i] = 0; d_deg_out[i] = 0; }
    if (i < HID) {
        d_bn1s[i] = 0.f; d_bn1q[i] = 0.f;
        d_bn2s[i] = 0.f; d_bn2q[i] = 0.f;
        d_bn3s[i] = 0.f; d_bn3q[i] = 0.f;
    }
    if (i == 0) d_meanAcc = 0.f;
}

// degree counting: spread atomics only (80k addresses)
__global__ void k_deg(const int* __restrict__ src, const int* __restrict__ dst) {
    int e = blockIdx.x * blockDim.x + threadIdx.x;
    if (e >= N_EDGES) return;
    atomicAdd(&d_deg_out[src[e]], 1);
    atomicAdd(&d_deg_in[dst[e]], 1);
}

__global__ void k_node() {
    int i = blockIdx.x * blockDim.x + threadIdx.x;
    if (i >= N_NODES) return;
    int di = d_deg_in[i], dout = d_deg_out[i];
    float ii = rsqrtf((float)(di   > 1 ? di   : 1));
    float io = rsqrtf((float)(dout > 1 ? dout : 1));
    d_inv_in[i] = ii;
    d_inv_out[i] = io;
    int cls = di < (IND - 1) ? di : (IND - 1);
    d_ninfo[i] = make_float2(io, (float)cls);
}

// per-graph edge totals: one warp per graph (parallel across SMs)
__global__ void k_gsum() {
    int wp = threadIdx.x >> 5, lane = threadIdx.x & 31;
    int g = blockIdx.x * 8 + wp;
    if (g >= BATCH) return;
    const int* p = d_deg_in + g * NPG;
    int s = 0;
    for (int j = lane; j < NPG; j += 32) s += p[j];
    for (int o = 16; o > 0; o >>= 1) s += __shfl_xor_sync(0xffffffffu, s, o);
    if (lane == 0) d_gsum[g] = s;
}

// scan of 800 per-graph totals -> d_goff (cheap: 800 loads)
__global__ void k_gscan() {
    __shared__ int s[1024];
    int t = threadIdx.x;
    s[t] = (t < BATCH) ? d_gsum[t] : 0;
    __syncthreads();
    for (int o = 1; o < 1024; o <<= 1) {
        int v = (t >= o) ? s[t - o] : 0;
        __syncthreads();
        s[t] += v;
        __syncthreads();
    }
    if (t < BATCH) d_goff[t + 1] = s[t];
    if (t == 0) d_goff[0] = 0;
}

// per-graph node offsets (scan of 100 in-degrees) -> d_off, d_cur
__global__ void k_offsets() {
    __shared__ int s[NPG];
    int g = blockIdx.x, t = threadIdx.x;
    int deg = 0;
    if (t < NPG) { deg = d_deg_in[g * NPG + t]; s[t] = deg; }
    __syncthreads();
    for (int o = 1; o < NPG; o <<= 1) {
        int v = 0;
        if (t < NPG && t >= o) v = s[t - o];
        __syncthreads();
        if (t < NPG && t >= o) s[t] += v;
        __syncthreads();
    }
    if (t < NPG) {
        int off = d_goff[g] + s[t] - deg;
        d_off[g * NPG + t] = off;
        d_cur[g * NPG + t] = off;
    }
    if (g == 0 && t == 0) d_off[N_NODES] = N_EDGES;
}

// single edge pass: CSR scatter (80k cursors) + 20-class scatter
__global__ void k_scatter(const int* __restrict__ src, const int* __restrict__ dst) {
    int e = blockIdx.x * blockDim.x + threadIdx.x;
    if (e >= N_EDGES) return;
    int s = src[e], d = dst[e];
    int pos = atomicAdd(&d_cur[d], 1);
    d_esrc[pos] = s % NPG;               // src local id (same graph as dst)
    float2 ni = d_ninfo[s];
    atomicAdd(&d_acc20[d * IND + (int)ni.y], ni.x);
}

// bn1 stats only (pre1 never stored)
#define L1N 64
__global__ void k_l1stats(const float* __restrict__ W1, const float* __restrict__ b1) {
    __shared__ float a20[L1N * IND];
    __shared__ float invs[L1N];
    int c = threadIdx.x;
    int base = blockIdx.x * L1N;
    for (int idx = c; idx < L1N * IND; idx += HID)
        a20[idx] = d_acc20[base * IND + idx];
    if (c < L1N) invs[c] = d_inv_in[base + c];
    float w1r[IND];
#pragma unroll
    for (int k = 0; k < IND; k++) w1r[k] = W1[k * HID + c];
    float b1c = b1[c];
    __syncthreads();
    float s1 = 0.f, s2 = 0.f;
    for (int nd = 0; nd < L1N; nd++) {
        float acc = 0.f;
#pragma unroll
        for (int k = 0; k < IND; k++) acc += a20[nd * IND + k] * w1r[k];
        float y = acc * invs[nd] + b1c;
        s1 += y; s2 += y * y;
    }
    atomicAdd(&d_bn1s[c], s1);
    atomicAdd(&d_bn1q[c], s2);
}

// ---------- layer 2: persistent; recompute pre1 from acc20, agg, 3xTF32 MMA ----------
#define L2T 512
__global__ __launch_bounds__(L2T, 1)
void k_layer2(const float* __restrict__ g1, const float* __restrict__ be1,
              const float* __restrict__ W1, const float* __restrict__ b1,
              const float* __restrict__ W2, const float* __restrict__ b2) {
    extern __shared__ float smem[];
    float*    W2s    = smem;                       // 128*136
    float*    aggf   = W2s + 128 * 136;            // 112*132
    float*    h1m    = aggf + 112 * 132;           // 100*128
    float*    W1s    = h1m + 100 * 128;            // 20*128
    float*    a20s   = W1s + 20 * 128;             // 100*20
    float*    alpha  = a20s + 100 * IND;           // 128 (bn1 scale)
    float*    beta1p = alpha + 128;                // 128 (alpha*b1 + beta)
    float*    b2s    = beta1p + 128;               // 128
    float*    invin  = b2s + 128;                  // 100
    float*    invout = invin + 100;                // 100
    int*      off_s  = (int*)(invout + 100);       // 104
    int*      esrc_s = off_s + 104;                // ECAP

    int tid = threadIdx.x;
    int wp = tid >> 5, lane = tid & 31;

    // one-time init
    for (int idx = tid; idx < HID * HID; idx += L2T) {
        int k = idx >> 7, n = idx & 127;
        W2s[k * 136 + n] = W2[idx];
    }
    for (int idx = tid; idx < IND * HID; idx += L2T)
        W1s[idx] = W1[idx];
    if (tid < HID) {
        float invN = 1.f / (float)N_NODES;
        float mu = d_bn1s[tid] * invN;
        float var = d_bn1q[tid] * invN - mu * mu;
        float rstd = rsqrtf(var + EPS);
        float a = g1[tid] * rstd;
        alpha[tid] = a;
        beta1p[tid] = a * b1[tid] + (be1[tid] - mu * a);
        b2s[tid] = b2[tid];
    }
    for (int idx = tid; idx < 12 * 132; idx += L2T)
        aggf[100 * 132 + idx] = 0.f;               // zero pad rows 100..111
    __syncthreads();

    // per-thread persistent W1 column + bn consts
    int cc = tid & 127;
    int grp = tid >> 7;                            // 0..3 -> li block of 25
    float w1c[IND];
#pragma unroll
    for (int k = 0; k < IND; k++) w1c[k] = W1s[k * HID + cc];
    float alpha_c = alpha[cc], beta_c = beta1p[cc];

    for (int g = blockIdx.x; g < BATCH; g += gridDim.x) {
        // phase 0: stage per-graph data
        for (int idx = tid; idx < NPG * IND; idx += L2T)
            a20s[idx] = d_acc20[g * NPG * IND + idx];
        if (tid < NPG) {
            invin[tid]  = d_inv_in[g * NPG + tid];
            invout[tid] = d_inv_out[g * NPG + tid];
        }
        if (tid >= 128 && tid - 128 <= NPG) off_s[tid - 128] = d_off[g * NPG + tid - 128];
        int eB = d_off[g * NPG];
        int eE = d_off[g * NPG + NPG];
        int cnt = eE - eB;
        for (int idx = tid; idx < cnt && idx < ECAP; idx += L2T)
            esrc_s[idx] = d_esrc[eB + idx];
        __syncthreads();

        // phase a: recompute pre1 -> bn1 -> elu -> *inv_out -> h1m
        for (int li = grp * 25; li < grp * 25 + 25; li++) {
            float acc = 0.f;
#pragma unroll
            for (int k = 0; k < IND; k++) acc += a20s[li * IND + k] * w1c[k];
            float h = fast_elu(acc * (alpha_c * invin[li]) + beta_c) * invout[li];
            h1m[li * HID + cc] = h;
        }
        __syncthreads();

        // phase b: aggregation (warp per node, float4 channels)
        if (cnt <= ECAP) {
            for (int li = wp; li < NPG; li += 16) {
                int lo = off_s[li], hi = off_s[li + 1];
                float4 acc = make_float4(0.f, 0.f, 0.f, 0.f);
                for (int e = lo; e < hi; e++) {
                    int sl = esrc_s[e - eB];
                    float4 v = ((const float4*)h1m)[sl * 32 + lane];
                    acc.x += v.x; acc.y += v.y; acc.z += v.z; acc.w += v.w;
                }
                float ii = invin[li];
                float4 o = make_float4(acc.x * ii, acc.y * ii, acc.z * ii, acc.w * ii);
                *(float4*)&aggf[li * 132 + lane * 4] = o;
            }
        } else {
            for (int li = wp; li < NPG; li += 16) {
                int lo = off_s[li], hi = off_s[li + 1];
                float4 acc = make_float4(0.f, 0.f, 0.f, 0.f);
                for (int e = lo; e < hi; e++) {
                    int sl = d_esrc[e];
                    float4 v = ((const float4*)h1m)[sl * 32 + lane];
                    acc.x += v.x; acc.y += v.y; acc.z += v.z; acc.w += v.w;
                }
                float ii = invin[li];
                float4 o = make_float4(acc.x * ii, acc.y * ii, acc.z * ii, acc.w * ii);
                *(float4*)&aggf[li * 132 + lane * 4] = o;
            }
        }
        __syncthreads();

        // phase c: 3xTF32 MMA — 14 warps: (mtile 0..6) x (nhalf 0..1)
        if (wp < 14) {
            int mt = wp >> 1, nh = wp & 1;
            int row = mt * 16 + (lane >> 2);
            int kk = lane & 3;
            float acc[8][4];
#pragma unroll
            for (int nt = 0; nt < 8; nt++)
#pragma unroll
                for (int q = 0; q < 4; q++) acc[nt][q] = 0.f;
#pragma unroll
            for (int k0 = 0; k0 < HID; k0 += 8) {
                float af0 = aggf[row * 132 + k0 + kk];
                float af1 = aggf[(row + 8) * 132 + k0 + kk];
                float af2 = aggf[row * 132 + k0 + kk + 4];
                float af3 = aggf[(row + 8) * 132 + k0 + kk + 4];
                unsigned ah0, al0, ah1, al1, ah2, al2, ah3, al3;
                tf32split(af0, ah0, al0);
                tf32split(af1, ah1, al1);
                tf32split(af2, ah2, al2);
                tf32split(af3, ah3, al3);
#pragma unroll
                for (int nt = 0; nt < 8; nt++) {
                    int ncol = nh * 64 + nt * 8 + (lane >> 2);
                    float bf0 = W2s[(k0 + kk) * 136 + ncol];
                    float bf1 = W2s[(k0 + kk + 4) * 136 + ncol];
                    unsigned bh0, bl0, bh1, bl1;
                    tf32split(bf0, bh0, bl0);
                    tf32split(bf1, bh1, bl1);
                    asm volatile(
                        "mma.sync.aligned.m16n8k8.row.col.f32.tf32.tf32.f32 "
                        "{%0,%1,%2,%3}, {%4,%5,%6,%7}, {%8,%9}, {%0,%1,%2,%3};"
                        : "+f"(acc[nt][0]), "+f"(acc[nt][1]),
                          "+f"(acc[nt][2]), "+f"(acc[nt][3])
                        : "r"(ah0), "r"(ah1), "r"(ah2), "r"(ah3), "r"(bh0), "r"(bh1));
                    asm volatile(
                        "mma.sync.aligned.m16n8k8.row.col.f32.tf32.tf32.f32 "
                        "{%0,%1,%2,%3}, {%4,%5,%6,%7}, {%8,%9}, {%0,%1,%2,%3};"
                        : "+f"(acc[nt][0]), "+f"(acc[nt][1]),
                          "+f"(acc[nt][2]), "+f"(acc[nt][3])
                        : "r"(al0), "r"(al1), "r"(al2), "r"(al3), "r"(bh0), "r"(bh1));
                    asm volatile(
                        "mma.sync.aligned.m16n8k8.row.col.f32.tf32.tf32.f32 "
                        "{%0,%1,%2,%3}, {%4,%5,%6,%7}, {%8,%9}, {%0,%1,%2,%3};"
                        : "+f"(acc[nt][0]), "+f"(acc[nt][1]),
                          "+f"(acc[nt][2]), "+f"(acc[nt][3])
                        : "r"(ah0), "r"(ah1), "r"(ah2), "r"(ah3), "r"(bl0), "r"(bl1));
                }
            }
            long gi0 = ((long)g * NPG + row) * HID;
            long gi1 = ((long)g * NPG + row + 8) * HID;
#pragma unroll
            for (int nt = 0; nt < 8; nt++) {
                int c0 = nh * 64 + nt * 8 + 2 * (lane & 3);
                float bx = b2s[c0], by = b2s[c0 + 1];
                if (row < NPG)
                    *(float2*)&d_pre[gi0 + c0] = make_float2(acc[nt][0] + bx, acc[nt][1] + by);
                if (row + 8 < NPG)
                    *(float2*)&d_pre[gi1 + c0] = make_float2(acc[nt][2] + bx, acc[nt][3] + by);
            }
        }
        __syncthreads();
    }
}

__global__ void k_bn2stats() {
    int c = threadIdx.x;
    float s = 0.f, q = 0.f;
    for (int r = blockIdx.x; r < N_NODES; r += gridDim.x) {
        float v = d_pre[r * HID + c];
        s += v; q += v * v;
    }
    atomicAdd(&d_bn2s[c], s);
    atomicAdd(&d_bn2q[c], q);
}

// per-graph tail: bn2+elu -> h2(smem); t = inv_out*(h2.Wv); d from CSR; vec readout
#define GT_T 128
__global__ __launch_bounds__(GT_T)
void k_gtail(const float* __restrict__ g2, const float* __restrict__ be2,
             const float* __restrict__ Wv, const float* __restrict__ bv) {
    __shared__ float h2s[NPG * HID];   // 51200 B
    __shared__ float al2[HID];
    __shared__ float bt2[HID];
    __shared__ float ts[NPG];
    __shared__ float ds[NPG];
    __shared__ float ws[4];
    int g = blockIdx.x, tid = threadIdx.x;
    int wp = tid >> 5, lane = tid & 31;

    if (tid < HID) {
        float invN = 1.f / (float)N_NODES;
        float mu = d_bn2s[tid] * invN;
        float var = d_bn2q[tid] * invN - mu * mu;
        float a = g2[tid] * rsqrtf(var + EPS);
        al2[tid] = a;
        bt2[tid] = be2[tid] - mu * a;
    }
    __syncthreads();

    // phase 1: load pre2 slice, bn + elu -> h2s
    const float4* P = (const float4*)(d_pre + (long)g * NPG * HID);
    for (int idx = tid; idx < NPG * 32; idx += GT_T) {
        float4 v = P[idx];
        int c4 = (idx & 31) * 4;
        float4 a4 = *(const float4*)&al2[c4];
        float4 b4 = *(const float4*)&bt2[c4];
        v.x = fast_elu(v.x * a4.x + b4.x);
        v.y = fast_elu(v.y * a4.y + b4.y);
        v.z = fast_elu(v.z * a4.z + b4.z);
        v.w = fast_elu(v.w * a4.w + b4.w);
        ((float4*)h2s)[idx] = v;
    }
    __syncthreads();

    // phase 2: t[j] = inv_out * dot(h2[j], Wv)  (warp per node)
    float4 w4 = ((const float4*)Wv)[lane];
    for (int j = wp; j < NPG; j += 4) {
        float4 h = ((const float4*)h2s)[j * 32 + lane];
        float s = h.x * w4.x + h.y * w4.y + h.z * w4.z + h.w * w4.w;
        for (int o = 16; o > 0; o >>= 1) s += __shfl_xor_sync(0xffffffffu, s, o);
        if (lane == 0) ts[j] = s * d_inv_out[g * NPG + j];
    }
    __syncthreads();

    // phase 3: d[i] = inv_in*sum(t[src]) + bv
    float bv0 = bv[0];
    if (tid < NPG) {
        int i = g * NPG + tid;
        int lo = d_off[i], hi = d_off[i + 1];
        float a = 0.f;
        for (int e = lo; e < hi; e++) a += ts[d_esrc[e]];
        ds[tid] = d_inv_in[i] * a + bv0;
    }
    __syncthreads();

    // phase 4: vec[g][c] = sum_j d[j] * h2[j][c]
    float acc = 0.f;
    for (int j = 0; j < NPG; j++)
        acc += ds[j] * h2s[j * HID + tid];
    d_vec[g * HID + tid] = acc;
    float s = acc;
    for (int o = 16; o > 0; o >>= 1) s += __shfl_xor_sync(0xffffffffu, s, o);
    if (lane == 0) ws[wp] = s;
    __syncthreads();
    if (tid == 0) atomicAdd(&d_meanAcc, ws[0] + ws[1] + ws[2] + ws[3]);
}

// shrink+tanh fused into FC: z = tanh(shrink(vec)) @ Wg + bg ; bn3 stats
#define FCR 8
__global__ void k_fc(const float* __restrict__ Wg, const float* __restrict__ bg) {
    __shared__ float rowS[FCR][HID];
    int c = threadIdx.x;
    int r0 = blockIdx.x * FCR;
    float mean = d_meanAcc * (1.f / (BATCH * HID));
    for (int nd = 0; nd < FCR; nd++) {
        float x = d_vec[(r0 + nd) * HID + c];
        float sv = fmaxf(x - mean, 0.f) - fmaxf(-x - mean, 0.f);
        rowS[nd][c] = tanhf(sv);
    }
    __syncthreads();
    float acc[FCR];
    float bgc = bg[c];
#pragma unroll
    for (int nd = 0; nd < FCR; nd++) acc[nd] = bgc;
    for (int k = 0; k < HID; k += 4) {
        float w0 = Wg[(k + 0) * HID + c];
        float w1 = Wg[(k + 1) * HID + c];
        float w2 = Wg[(k + 2) * HID + c];
        float w3 = Wg[(k + 3) * HID + c];
#pragma unroll
        for (int nd = 0; nd < FCR; nd++) {
            float4 a = *reinterpret_cast<float4*>(&rowS[nd][k]);
            acc[nd] += a.x * w0 + a.y * w1 + a.z * w2 + a.w * w3;
        }
    }
    float s1 = 0.f, s2 = 0.f;
#pragma unroll
    for (int nd = 0; nd < FCR; nd++) {
        float y = acc[nd];
        d_z[(r0 + nd) * HID + c] = y;
        s1 += y; s2 += y * y;
    }
    atomicAdd(&d_bn3s[c], s1);
    atomicAdd(&d_bn3q[c], s2);
}

__global__ void k_final(const float* __restrict__ g3, const float* __restrict__ be3,
                        const float* __restrict__ Wc, const float* __restrict__ bc,
                        float* __restrict__ out) {
    __shared__ float hs[HID];
    int b = blockIdx.x, c = threadIdx.x;
    float inv = 1.f / (float)BATCH;
    float mu = d_bn3s[c] * inv;
    float var = d_bn3q[c] * inv - mu * mu;
    float rstd = rsqrtf(var + EPS);
    float v = tanhf((d_z[b * HID + c] - mu) * rstd * g3[c] + be3[c]);
    hs[c] = v;
    __syncthreads();
    if (c < NC) {
        float a = bc[c];
        for (int k = 0; k < HID; k++)
            a += hs[k] * Wc[k * NC + c];
        out[b * NC + c] = tanhf(a);
    }
}

// ---------------- launch ----------------
extern "C" void kernel_launch(void* const* d_in, const int* in_sizes, int n_in,
                              void* d_out, int out_size) {
    const int*   src = (const int*)d_in[0];
    const int*   dst = (const int*)d_in[1];
    const float* W1  = (const float*)d_in[3];
    const float* b1  = (const float*)d_in[4];
    const float* g1  = (const float*)d_in[5];
    const float* be1 = (const float*)d_in[6];
    const float* W2  = (const float*)d_in[7];
    const float* b2  = (const float*)d_in[8];
    const float* g2  = (const float*)d_in[9];
    const float* be2 = (const float*)d_in[10];
    const float* Wv  = (const float*)d_in[11];
    const float* bv  = (const float*)d_in[12];
    const float* Wg  = (const float*)d_in[15];
    const float* bg  = (const float*)d_in[16];
    const float* g3  = (const float*)d_in[17];
    const float* be3 = (const float*)d_in[18];
    const float* Wc  = (const float*)d_in[19];
    const float* bc  = (const float*)d_in[20];
    float* out = (float*)d_out;

    static int smem_set = 0;
    const int L2_SMEM = (128 * 136 + 112 * 132 + 100 * 128 + 20 * 128 + 100 * IND
                         + 3 * 128 + 2 * 100) * 4 + 104 * 4 + ECAP * 4;
    if (!smem_set) {
        cudaFuncSetAttribute(k_layer2, cudaFuncAttributeMaxDynamicSharedMemorySize, L2_SMEM);
        smem_set = 1;
    }

    k_zero<<<(N_NODES * IND + 255) / 256, 256>>>();
    k_deg<<<(N_EDGES + 255) / 256, 256>>>(src, dst);
    k_node<<<(N_NODES + 1023) / 1024, 1024>>>();
    k_gsum<<<BATCH / 8, 256>>>();
    k_gscan<<<1, 1024>>>();
    k_offsets<<<BATCH, 128>>>();
    k_scatter<<<(N_EDGES + 255) / 256, 256>>>(src, dst);
    k_l1stats<<<N_NODES / L1N, HID>>>(W1, b1);
    k_layer2<<<148, L2T, L2_SMEM>>>(g1, be1, W1, b1, W2, b2);
    k_bn2stats<<<400, HID>>>();
    k_gtail<<<BATCH, GT_T>>>(g2, be2, Wv, bv);
    k_fc<<<BATCH / FCR, HID>>>(Wg, bg);
    k_final<<<BATCH, HID>>>(g3, be3, Wc, bc, out);
}